// round 8
// baseline (speedup 1.0000x reference)
#include <cuda_runtime.h>
#include <cuda_bf16.h>
#include <math.h>

#define MAXN 100000
#define MAXE 1600000
#define MAXG 500
#define LL 8
#define BN_EPS 1e-5f

// ---------------- device scratch ----------------
__device__ __nv_bfloat162 g_hh[LL][(size_t)MAXN * 32];  // bf16 features per layer (JK)
__device__ float g_z[(size_t)MAXN * 64];                 // z = (1+eps)*h + agg (fp32)
__device__ int g_deg[MAXN + 1];
__device__ int g_off[MAXN + 2];
__device__ int g_pos[MAXN + 1];
__device__ int g_csr[MAXE];
__device__ int g_bsum[1024];

// ---------------- helpers ----------------
__device__ __forceinline__ unsigned long long pack2(float a, float b) {
    unsigned long long r;
    asm("mov.b64 %0, {%1, %2};" : "=l"(r) : "f"(a), "f"(b));
    return r;
}
__device__ __forceinline__ void unpack2(unsigned long long v, float& a, float& b) {
    asm("mov.b64 {%0, %1}, %2;" : "=f"(a), "=f"(b) : "l"(v));
}
__device__ __forceinline__ void fma2(unsigned long long& acc, unsigned long long a, unsigned long long b) {
    asm("fma.rn.f32x2 %0, %1, %2, %0;" : "+l"(acc) : "l"(a), "l"(b));
}
// split (x,y) into bf16 hi pair + bf16 lo (residual) pair
__device__ __forceinline__ void bfsplit(float x, float y, unsigned& hi, unsigned& lo) {
    __nv_bfloat162 h = __floats2bfloat162_rn(x, y);
    float rx = x - __bfloat162float(h.x);
    float ry = y - __bfloat162float(h.y);
    __nv_bfloat162 l = __floats2bfloat162_rn(rx, ry);
    hi = *reinterpret_cast<unsigned*>(&h);
    lo = *reinterpret_cast<unsigned*>(&l);
}
__device__ __forceinline__ void mma16(float (&c)[4], unsigned a0, unsigned a1, unsigned a2, unsigned a3,
                                      unsigned b0, unsigned b1) {
    asm volatile("mma.sync.aligned.m16n8k16.row.col.f32.bf16.bf16.f32 "
                 "{%0,%1,%2,%3},{%4,%5,%6,%7},{%8,%9},{%0,%1,%2,%3};"
                 : "+f"(c[0]), "+f"(c[1]), "+f"(c[2]), "+f"(c[3])
                 : "r"(a0), "r"(a1), "r"(a2), "r"(a3), "r"(b0), "r"(b1));
}

// ============ CSR build ============
__global__ __launch_bounds__(256) void deg_count(const int* __restrict__ ei, int E, int* __restrict__ deg) {
    int e = blockIdx.x * 256 + threadIdx.x;
    if (e >= E) return;
    atomicAdd(&deg[ei[E + e]], 1);
}

__global__ __launch_bounds__(512) void chunk_sum(const int* __restrict__ deg, int n, int* __restrict__ bsum) {
    __shared__ int sh[512];
    int t = threadIdx.x;
    int i = blockIdx.x * 512 + t;
    sh[t] = (i < n) ? deg[i] : 0;
    __syncthreads();
#pragma unroll
    for (int s = 256; s > 0; s >>= 1) {
        if (t < s) sh[t] += sh[t + s];
        __syncthreads();
    }
    if (t == 0) bsum[blockIdx.x] = sh[0];
}

__global__ __launch_bounds__(1024) void scan_bsum(int* __restrict__ bsum, int nb) {
    __shared__ int sh[1024];
    int t = threadIdx.x;
    int v = (t < nb) ? bsum[t] : 0;
    sh[t] = v;
    __syncthreads();
    for (int d = 1; d < 1024; d <<= 1) {
        int add = (t >= d) ? sh[t - d] : 0;
        __syncthreads();
        sh[t] += add;
        __syncthreads();
    }
    if (t < nb) bsum[t] = sh[t] - v;   // exclusive
}

__global__ __launch_bounds__(512) void chunk_scan(const int* __restrict__ deg, int n,
                                                  const int* __restrict__ bsum,
                                                  int* __restrict__ off, int* __restrict__ pos) {
    __shared__ int sh[512];
    int t = threadIdx.x;
    int i = blockIdx.x * 512 + t;
    int v = (i < n) ? deg[i] : 0;
    sh[t] = v;
    __syncthreads();
    for (int d = 1; d < 512; d <<= 1) {
        int add = (t >= d) ? sh[t - d] : 0;
        __syncthreads();
        sh[t] += add;
        __syncthreads();
    }
    if (i < n) {
        int ex = sh[t] - v + bsum[blockIdx.x];
        off[i] = ex;
        pos[i] = ex;
    }
}

__global__ __launch_bounds__(256) void csr_scatter(const int* __restrict__ ei, int E,
                                                   int* __restrict__ pos, int* __restrict__ csr) {
    int e = blockIdx.x * 256 + threadIdx.x;
    if (e >= E) return;
    int src = ei[e];
    int dst = ei[E + e];
    int p = atomicAdd(&pos[dst], 1);
    csr[p] = src;
}

// ============ CSR aggregation (bf16 rows -> fp32 z) ============
__device__ __forceinline__ void addrow(float4 v, float* acc) {
    const __nv_bfloat162* h = reinterpret_cast<const __nv_bfloat162*>(&v);
#pragma unroll
    for (int j = 0; j < 4; ++j) {
        float2 f = __bfloat1622float2(h[j]);
        acc[2 * j]     += f.x;
        acc[2 * j + 1] += f.y;
    }
}

// 8 threads per node, each thread covers 8 contiguous features (16B).
__global__ __launch_bounds__(256) void csr_agg_h(const int* __restrict__ off, const int* __restrict__ csr,
                                                 const __nv_bfloat162* __restrict__ hh, float* __restrict__ z,
                                                 const float* __restrict__ eps, int N) {
    int t = blockIdx.x * 256 + threadIdx.x;
    int n = t >> 3;
    if (n >= N) return;
    int q = t & 7;
    const float4* hq = reinterpret_cast<const float4*>(hh) + q;
    float acc[8];
#pragma unroll
    for (int j = 0; j < 8; ++j) acc[j] = 0.f;
    int b = off[n], e = off[n + 1];
    int i = b;
    for (; i + 8 <= e; i += 8) {
        int idx[8];
#pragma unroll
        for (int u = 0; u < 8; ++u) idx[u] = __ldg(&csr[i + u]);
        float4 v[8];
#pragma unroll
        for (int u = 0; u < 8; ++u) v[u] = hq[idx[u] * 8];
#pragma unroll
        for (int u = 0; u < 8; ++u) addrow(v[u], acc);
    }
    for (; i + 4 <= e; i += 4) {
        int i0 = __ldg(&csr[i]);
        int i1 = __ldg(&csr[i + 1]);
        int i2 = __ldg(&csr[i + 2]);
        int i3 = __ldg(&csr[i + 3]);
        float4 v0 = hq[i0 * 8];
        float4 v1 = hq[i1 * 8];
        float4 v2 = hq[i2 * 8];
        float4 v3 = hq[i3 * 8];
        addrow(v0, acc);
        addrow(v1, acc);
        addrow(v2, acc);
        addrow(v3, acc);
    }
    for (; i < e; ++i) addrow(hq[__ldg(&csr[i]) * 8], acc);

    float ev = 1.0f + eps[0];
    float4 sv = hq[n * 8];
    const __nv_bfloat162* sh2 = reinterpret_cast<const __nv_bfloat162*>(&sv);
    float4 o0, o1;
    {
        float2 f0 = __bfloat1622float2(sh2[0]);
        float2 f1 = __bfloat1622float2(sh2[1]);
        float2 f2 = __bfloat1622float2(sh2[2]);
        float2 f3 = __bfloat1622float2(sh2[3]);
        o0.x = fmaf(ev, f0.x, acc[0]);
        o0.y = fmaf(ev, f0.y, acc[1]);
        o0.z = fmaf(ev, f1.x, acc[2]);
        o0.w = fmaf(ev, f1.y, acc[3]);
        o1.x = fmaf(ev, f2.x, acc[4]);
        o1.y = fmaf(ev, f2.y, acc[5]);
        o1.z = fmaf(ev, f3.x, acc[6]);
        o1.w = fmaf(ev, f3.y, acc[7]);
    }
    float4* zp = reinterpret_cast<float4*>(z + (size_t)n * 64 + q * 8);
    zp[0] = o0;
    zp[1] = o1;
}

// scalar features (layer 0)
__global__ __launch_bounds__(256) void csr_agg1(const int* __restrict__ off, const int* __restrict__ csr,
                                                const float* __restrict__ x, float* __restrict__ agg, int N) {
    int n = blockIdx.x * 256 + threadIdx.x;
    if (n >= N) return;
    int b = off[n], e = off[n + 1];
    float s = 0.f;
    int i = b;
    for (; i + 4 <= e; i += 4) {
        float v0 = x[__ldg(&csr[i])];
        float v1 = x[__ldg(&csr[i + 1])];
        float v2 = x[__ldg(&csr[i + 2])];
        float v3 = x[__ldg(&csr[i + 3])];
        s += (v0 + v1) + (v2 + v3);
    }
    for (; i < e; ++i) s += x[__ldg(&csr[i])];
    agg[n] = s;
}

// ============ BN params ============
__device__ __forceinline__ void load_bn_params(float* prm, int tid,
        const float* b1, const float* g1, const float* be1, const float* m1, const float* v1,
        const float* b2, const float* g2, const float* be2, const float* m2, const float* v2) {
    if (tid < 64) {
        float s1 = g1[tid] * rsqrtf(v1[tid] + BN_EPS);
        prm[tid]       = b1[tid];
        prm[64 + tid]  = s1;
        prm[128 + tid] = fmaf(-m1[tid], s1, be1[tid]);
        float s2 = g2[tid] * rsqrtf(v2[tid] + BN_EPS);
        prm[192 + tid] = b2[tid];
        prm[256 + tid] = s2;
        prm[320 + tid] = fmaf(-m2[tid], s2, be2[tid]);
    }
}

// ============ tensor-core node MLP (layers 1..7), bf16x2 split 3-term ============
// shared layout (u32): W1hi[2304] W1lo[2304] W2hi[2304] W2lo[2304] zhi[4608] zlo[4608] prm(float)[384]
#define AS 36   // row pitch in u32 (32 data + 4 pad) -> banks (4*grp+tig)%32 all distinct
#define OFF_W1HI 0
#define OFF_W1LO 2304
#define OFF_W2HI 4608
#define OFF_W2LO 6912
#define OFF_ZHI  9216
#define OFF_ZLO  13824
#define OFF_PRM  18432
#define MMA_SMEM_U32 (18432 + 384)

__device__ __forceinline__ void warp_gemm_bf(const unsigned* __restrict__ Whi,
                                             const unsigned* __restrict__ Wlo,
                                             const unsigned* __restrict__ zhi,
                                             const unsigned* __restrict__ zlo,
                                             int warp, int lane, float acc[2][8][4]) {
    int tig = lane & 3;
    int grp = lane >> 2;
#pragma unroll
    for (int kk = 0; kk < 4; ++kk) {
        int k2a = kk * 8 + tig;
        int k2b = kk * 8 + 4 + tig;
        unsigned bh[8][2], bl[8][2];
#pragma unroll
        for (int nt = 0; nt < 8; ++nt) {
            int n = nt * 8 + grp;
            bh[nt][0] = Whi[n * AS + k2a];
            bh[nt][1] = Whi[n * AS + k2b];
            bl[nt][0] = Wlo[n * AS + k2a];
            bl[nt][1] = Wlo[n * AS + k2b];
        }
#pragma unroll
        for (int mt = 0; mt < 2; ++mt) {
            int r0 = warp * 32 + mt * 16 + grp;
            unsigned ah0 = zhi[r0 * AS + k2a];
            unsigned ah1 = zhi[(r0 + 8) * AS + k2a];
            unsigned ah2 = zhi[r0 * AS + k2b];
            unsigned ah3 = zhi[(r0 + 8) * AS + k2b];
            unsigned al0 = zlo[r0 * AS + k2a];
            unsigned al1 = zlo[(r0 + 8) * AS + k2a];
            unsigned al2 = zlo[r0 * AS + k2b];
            unsigned al3 = zlo[(r0 + 8) * AS + k2b];
#pragma unroll
            for (int nt = 0; nt < 8; ++nt) {
                mma16(acc[mt][nt], ah0, ah1, ah2, ah3, bh[nt][0], bh[nt][1]);
                mma16(acc[mt][nt], ah0, ah1, ah2, ah3, bl[nt][0], bl[nt][1]);
                mma16(acc[mt][nt], al0, al1, al2, al3, bh[nt][0], bh[nt][1]);
            }
        }
    }
}

__global__ __launch_bounds__(128) void gin_node_mma(
        const float* __restrict__ zsrc,
        __nv_bfloat162* __restrict__ houth,
        const float* __restrict__ W1, const float* __restrict__ b1,
        const float* __restrict__ g1, const float* __restrict__ be1,
        const float* __restrict__ m1, const float* __restrict__ v1,
        const float* __restrict__ W2, const float* __restrict__ b2,
        const float* __restrict__ g2, const float* __restrict__ be2,
        const float* __restrict__ m2, const float* __restrict__ v2, int N) {
    extern __shared__ unsigned smu[];
    unsigned* W1hi = smu + OFF_W1HI;
    unsigned* W1lo = smu + OFF_W1LO;
    unsigned* W2hi = smu + OFF_W2HI;
    unsigned* W2lo = smu + OFF_W2LO;
    unsigned* zhi  = smu + OFF_ZHI;
    unsigned* zlo  = smu + OFF_ZLO;
    float* prm = reinterpret_cast<float*>(smu + OFF_PRM);
    int tid = threadIdx.x;
    int warp = tid >> 5, lane = tid & 31;
    int tig = lane & 3, grp = lane >> 2;

    // weights -> shared, transposed to [n][k2] bf16x2 pairs, hi+lo split
    for (int idx = tid; idx < 2048; idx += 128) {
        int n = idx >> 5, k2 = idx & 31;
        int koff = (k2 * 2) * 64 + n;
        unsigned hi, lo;
        bfsplit(W1[koff], W1[koff + 64], hi, lo);
        W1hi[n * AS + k2] = hi;
        W1lo[n * AS + k2] = lo;
        bfsplit(W2[koff], W2[koff + 64], hi, lo);
        W2hi[n * AS + k2] = hi;
        W2lo[n * AS + k2] = lo;
    }
    load_bn_params(prm, tid, b1, g1, be1, m1, v1, b2, g2, be2, m2, v2);

    int n0 = blockIdx.x * 128;
    // per-warp zs fill: lane -> row (warp*32 + lane)
    {
        int row = warp * 32 + lane;
        int n = n0 + row;
        unsigned* zh = zhi + row * AS;
        unsigned* zl = zlo + row * AS;
        if (n < N) {
            const float4* zp = reinterpret_cast<const float4*>(zsrc) + (size_t)n * 16;
#pragma unroll
            for (int q = 0; q < 16; ++q) {
                float4 v = zp[q];
                unsigned hi, lo;
                bfsplit(v.x, v.y, hi, lo);
                zh[2 * q] = hi;
                zl[2 * q] = lo;
                bfsplit(v.z, v.w, hi, lo);
                zh[2 * q + 1] = hi;
                zl[2 * q + 1] = lo;
            }
        } else {
#pragma unroll
            for (int q = 0; q < 32; ++q) { zh[q] = 0; zl[q] = 0; }
        }
    }
    __syncthreads();

    float acc[2][8][4];
#pragma unroll
    for (int mt = 0; mt < 2; ++mt)
#pragma unroll
        for (int nt = 0; nt < 8; ++nt)
#pragma unroll
            for (int p = 0; p < 4; ++p) acc[mt][nt][p] = 0.f;

    warp_gemm_bf(W1hi, W1lo, zhi, zlo, warp, lane, acc);

    // BN1 + ReLU -> back into zs (warp-private rows), zero acc
#pragma unroll
    for (int nt = 0; nt < 8; ++nt) {
        int j = nt * 8 + 2 * tig;
        float b1a = prm[j],       b1b = prm[j + 1];
        float s1a = prm[64 + j],  s1b = prm[64 + j + 1];
        float t1a = prm[128 + j], t1b = prm[128 + j + 1];
        int k2 = nt * 4 + tig;
#pragma unroll
        for (int mt = 0; mt < 2; ++mt) {
            float* C = acc[mt][nt];
            int row = warp * 32 + mt * 16 + grp;
            float y0 = fmaf(fmaxf(C[0] + b1a, 0.f), s1a, t1a);
            float y1 = fmaf(fmaxf(C[1] + b1b, 0.f), s1b, t1b);
            float y2 = fmaf(fmaxf(C[2] + b1a, 0.f), s1a, t1a);
            float y3 = fmaf(fmaxf(C[3] + b1b, 0.f), s1b, t1b);
            unsigned hi, lo;
            bfsplit(y0, y1, hi, lo);
            zhi[row * AS + k2] = hi;
            zlo[row * AS + k2] = lo;
            bfsplit(y2, y3, hi, lo);
            zhi[(row + 8) * AS + k2] = hi;
            zlo[(row + 8) * AS + k2] = lo;
            C[0] = C[1] = C[2] = C[3] = 0.f;
        }
    }
    __syncwarp();

    warp_gemm_bf(W2hi, W2lo, zhi, zlo, warp, lane, acc);

    // BN2 + bf16 store
#pragma unroll
    for (int nt = 0; nt < 8; ++nt) {
        int j = nt * 8 + 2 * tig;
        float b2a = prm[192 + j], b2b = prm[192 + j + 1];
        float s2a = prm[256 + j], s2b = prm[256 + j + 1];
        float t2a = prm[320 + j], t2b = prm[320 + j + 1];
        int jc = j >> 1;
#pragma unroll
        for (int mt = 0; mt < 2; ++mt) {
            float* C = acc[mt][nt];
            int row = warp * 32 + mt * 16 + grp;
            int n = n0 + row;
            if (n < N) {
                float o0 = fmaf(fmaxf(C[0] + b2a, 0.f), s2a, t2a);
                float o1 = fmaf(fmaxf(C[1] + b2b, 0.f), s2b, t2b);
                houth[(size_t)n * 32 + jc] = __floats2bfloat162_rn(o0, o1);
            }
            if (n + 8 < N) {
                float o2 = fmaf(fmaxf(C[2] + b2a, 0.f), s2a, t2a);
                float o3 = fmaf(fmaxf(C[3] + b2b, 0.f), s2b, t2b);
                houth[(size_t)(n + 8) * 32 + jc] = __floats2bfloat162_rn(o2, o3);
            }
        }
    }
}

// ============ layer 0 (scalar input, FFMA path) ============
#define NODE0_SMEM_FLOATS (4096 + 384 + 64 + 128 * 65)

__device__ __forceinline__ void gemm_tile(const float* __restrict__ Wsh,
                                          const float* __restrict__ zs,
                                          int r, int c, unsigned long long acc[8][4]) {
    const float* zbase = zs + r * 8 * 65;
    const float* wbase = Wsh + c * 8;
#pragma unroll 2
    for (int k = 0; k < 64; ++k) {
        unsigned long long zz[8];
#pragma unroll
        for (int i = 0; i < 8; ++i) {
            float z = zbase[i * 65 + k];
            zz[i] = pack2(z, z);
        }
        ulonglong2 wa = *reinterpret_cast<const ulonglong2*>(wbase + k * 64);
        ulonglong2 wb = *reinterpret_cast<const ulonglong2*>(wbase + k * 64 + 4);
#pragma unroll
        for (int i = 0; i < 8; ++i) {
            fma2(acc[i][0], zz[i], wa.x);
            fma2(acc[i][1], zz[i], wa.y);
            fma2(acc[i][2], zz[i], wb.x);
            fma2(acc[i][3], zz[i], wb.y);
        }
    }
}

__global__ __launch_bounds__(128) void gin_node0(
        const float* __restrict__ x, const float* __restrict__ agg,
        __nv_bfloat162* __restrict__ houth, const float* __restrict__ eps,
        const float* __restrict__ W1f, const float* __restrict__ b1,
        const float* __restrict__ g1, const float* __restrict__ be1,
        const float* __restrict__ m1, const float* __restrict__ v1,
        const float* __restrict__ W2, const float* __restrict__ b2,
        const float* __restrict__ g2, const float* __restrict__ be2,
        const float* __restrict__ m2, const float* __restrict__ v2, int N) {
    extern __shared__ float sm[];
    float* W2s = sm;
    float* prm = sm + 4096;
    float* w1f = sm + 4480;
    float* zs  = sm + 4544;
    int tid = threadIdx.x;

    float4* w2d = reinterpret_cast<float4*>(W2s);
    const float4* w2g = reinterpret_cast<const float4*>(W2);
#pragma unroll
    for (int i = tid; i < 1024; i += 128) w2d[i] = w2g[i];
    if (tid < 64) w1f[tid] = W1f[tid];
    load_bn_params(prm, tid, b1, g1, be1, m1, v1, b2, g2, be2, m2, v2);
    __syncthreads();

    int n0 = blockIdx.x * 128;
    int n = n0 + tid;
    float* zrow = zs + tid * 65;
    if (n < N) {
        float ev = 1.0f + eps[0];
        float z = fmaf(ev, x[n], agg[n]);
#pragma unroll
        for (int j = 0; j < 64; ++j) {
            float y = fmaxf(fmaf(z, w1f[j], prm[j]), 0.f);
            zrow[j] = fmaf(y, prm[64 + j], prm[128 + j]);
        }
    } else {
#pragma unroll
        for (int j = 0; j < 64; ++j) zrow[j] = 0.f;
    }
    __syncthreads();

    int r = tid >> 3, c = tid & 7;
    unsigned long long acc[8][4];
#pragma unroll
    for (int i = 0; i < 8; ++i)
#pragma unroll
        for (int p = 0; p < 4; ++p) acc[i][p] = 0ull;
    gemm_tile(W2s, zs, r, c, acc);

    float4 b2a = *reinterpret_cast<const float4*>(prm + 192 + c * 8);
    float4 b2b = *reinterpret_cast<const float4*>(prm + 192 + c * 8 + 4);
    float4 s2a = *reinterpret_cast<const float4*>(prm + 256 + c * 8);
    float4 s2b = *reinterpret_cast<const float4*>(prm + 256 + c * 8 + 4);
    float4 t2a = *reinterpret_cast<const float4*>(prm + 320 + c * 8);
    float4 t2b = *reinterpret_cast<const float4*>(prm + 320 + c * 8 + 4);
#pragma unroll
    for (int i = 0; i < 8; ++i) {
        int nn = n0 + r * 8 + i;
        if (nn >= N) break;
        float f0, f1, f2, f3, f4, f5, f6, f7;
        unpack2(acc[i][0], f0, f1);
        unpack2(acc[i][1], f2, f3);
        unpack2(acc[i][2], f4, f5);
        unpack2(acc[i][3], f6, f7);
        __nv_bfloat162 p0 = __floats2bfloat162_rn(
            fmaf(fmaxf(f0 + b2a.x, 0.f), s2a.x, t2a.x), fmaf(fmaxf(f1 + b2a.y, 0.f), s2a.y, t2a.y));
        __nv_bfloat162 p1 = __floats2bfloat162_rn(
            fmaf(fmaxf(f2 + b2a.z, 0.f), s2a.z, t2a.z), fmaf(fmaxf(f3 + b2a.w, 0.f), s2a.w, t2a.w));
        __nv_bfloat162 p2 = __floats2bfloat162_rn(
            fmaf(fmaxf(f4 + b2b.x, 0.f), s2b.x, t2b.x), fmaf(fmaxf(f5 + b2b.y, 0.f), s2b.y, t2b.y));
        __nv_bfloat162 p3 = __floats2bfloat162_rn(
            fmaf(fmaxf(f6 + b2b.z, 0.f), s2b.z, t2b.z), fmaf(fmaxf(f7 + b2b.w, 0.f), s2b.w, t2b.w));
        uint4 u;
        u.x = *reinterpret_cast<unsigned*>(&p0);
        u.y = *reinterpret_cast<unsigned*>(&p1);
        u.z = *reinterpret_cast<unsigned*>(&p2);
        u.w = *reinterpret_cast<unsigned*>(&p3);
        reinterpret_cast<uint4*>(houth)[(size_t)nn * 8 + c] = u;
    }
}

// ============ fused mean-pool + classifier head ============
__device__ __forceinline__ int lbound(const int* __restrict__ a, int n, int v) {
    int lo = 0, hi = n;
    while (lo < hi) {
        int mid = (lo + hi) >> 1;
        if (a[mid] < v) lo = mid + 1; else hi = mid;
    }
    return lo;
}

__global__ __launch_bounds__(128) void pool_classify(
        const __nv_bfloat162* __restrict__ hh, size_t lstride,
        const int* __restrict__ batch, int N,
        const float* __restrict__ lw1, const float* __restrict__ lb1,
        const float* __restrict__ lw2, const float* __restrict__ lb2,
        float* __restrict__ out) {
    __shared__ float ps[512];
    __shared__ float hid[64];
    __shared__ float lg[3];
    __shared__ int rng[2];
    int g = blockIdx.x;
    int tid = threadIdx.x;
    if (tid == 0) rng[0] = lbound(batch, N, g);
    if (tid == 32) rng[1] = lbound(batch, N, g + 1);
    __syncthreads();
    int a = rng[0], b = rng[1];

    int l = tid >> 4, c = tid & 15;   // layer, 4-feature chunk
    const __nv_bfloat162* base = hh + (size_t)l * lstride + c * 2;
    float4 acc0 = make_float4(0.f, 0.f, 0.f, 0.f);
    float4 acc1 = make_float4(0.f, 0.f, 0.f, 0.f);
    int n = a;
    for (; n + 2 <= b; n += 2) {
        uint2 v0 = *reinterpret_cast<const uint2*>(base + (size_t)n * 32);
        uint2 v1 = *reinterpret_cast<const uint2*>(base + (size_t)(n + 1) * 32);
        float2 f00 = __bfloat1622float2(*reinterpret_cast<__nv_bfloat162*>(&v0.x));
        float2 f01 = __bfloat1622float2(*reinterpret_cast<__nv_bfloat162*>(&v0.y));
        float2 f10 = __bfloat1622float2(*reinterpret_cast<__nv_bfloat162*>(&v1.x));
        float2 f11 = __bfloat1622float2(*reinterpret_cast<__nv_bfloat162*>(&v1.y));
        acc0.x += f00.x; acc0.y += f00.y; acc0.z += f01.x; acc0.w += f01.y;
        acc1.x += f10.x; acc1.y += f10.y; acc1.z += f11.x; acc1.w += f11.y;
    }
    if (n < b) {
        uint2 v0 = *reinterpret_cast<const uint2*>(base + (size_t)n * 32);
        float2 f00 = __bfloat1622float2(*reinterpret_cast<__nv_bfloat162*>(&v0.x));
        float2 f01 = __bfloat1622float2(*reinterpret_cast<__nv_bfloat162*>(&v0.y));
        acc0.x += f00.x; acc0.y += f00.y; acc0.z += f01.x; acc0.w += f01.y;
    }
    int cnt = b - a;
    float inv = 1.0f / (float)(cnt > 1 ? cnt : 1);
    int fo = l * 64 + c * 4;
    ps[fo]     = (acc0.x + acc1.x) * inv;
    ps[fo + 1] = (acc0.y + acc1.y) * inv;
    ps[fo + 2] = (acc0.z + acc1.z) * inv;
    ps[fo + 3] = (acc0.w + acc1.w) * inv;
    __syncthreads();

    if (tid < 64) {
        float s = lb1[tid];
#pragma unroll 8
        for (int k = 0; k < 512; ++k) s = fmaf(ps[k], lw1[k * 64 + tid], s);
        hid[tid] = fmaxf(s, 0.f);
    }
    __syncthreads();
    if (tid < 3) {
        float s = lb2[tid];
#pragma unroll
        for (int j = 0; j < 64; ++j) s = fmaf(hid[j], lw2[j * 3 + tid], s);
        lg[tid] = s;
    }
    __syncthreads();
    if (tid == 0) {
        float m = fmaxf(lg[0], fmaxf(lg[1], lg[2]));
        float e = expf(lg[0] - m) + expf(lg[1] - m) + expf(lg[2] - m);
        float lse = m + logf(e);
        out[g * 3 + 0] = lg[0] - lse;
        out[g * 3 + 1] = lg[1] - lse;
        out[g * 3 + 2] = lg[2] - lse;
    }
}

// ---------------- launcher ----------------
extern "C" void kernel_launch(void* const* d_in, const int* in_sizes, int n_in,
                              void* d_out, int out_size) {
    const float* x     = (const float*)d_in[0];
    const int*   ei    = (const int*)d_in[1];
    const int*   batch = (const int*)d_in[2];
    int bi = (in_sizes[3] == 1) ? 4 : 3;
    const float* eps  = (const float*)d_in[bi + 0];
    const float* W1f  = (const float*)d_in[bi + 1];
    const float* W1r  = (const float*)d_in[bi + 2];
    const float* b1   = (const float*)d_in[bi + 3];
    const float* g1   = (const float*)d_in[bi + 4];
    const float* be1  = (const float*)d_in[bi + 5];
    const float* m1   = (const float*)d_in[bi + 6];
    const float* v1   = (const float*)d_in[bi + 7];
    const float* W2   = (const float*)d_in[bi + 8];
    const float* b2   = (const float*)d_in[bi + 9];
    const float* g2   = (const float*)d_in[bi + 10];
    const float* be2  = (const float*)d_in[bi + 11];
    const float* m2   = (const float*)d_in[bi + 12];
    const float* v2   = (const float*)d_in[bi + 13];
    const float* lw1  = (const float*)d_in[bi + 14];
    const float* lb1  = (const float*)d_in[bi + 15];
    const float* lw2  = (const float*)d_in[bi + 16];
    const float* lb2  = (const float*)d_in[bi + 17];

    int N = in_sizes[0];
    int E = in_sizes[1] / 2;
    int G = out_size / 3;
    if (N > MAXN) N = MAXN;
    if (E > MAXE) E = MAXE;
    if (G > MAXG) G = MAXG;

    __nv_bfloat162* hh;
    float* z;
    int *deg, *off, *pos, *csr, *bsum;
    cudaGetSymbolAddress((void**)&hh, g_hh);
    cudaGetSymbolAddress((void**)&z, g_z);
    cudaGetSymbolAddress((void**)&deg, g_deg);
    cudaGetSymbolAddress((void**)&off, g_off);
    cudaGetSymbolAddress((void**)&pos, g_pos);
    cudaGetSymbolAddress((void**)&csr, g_csr);
    cudaGetSymbolAddress((void**)&bsum, g_bsum);
    const size_t lstride = (size_t)MAXN * 32;

    cudaFuncSetAttribute(gin_node_mma, cudaFuncAttributeMaxDynamicSharedMemorySize,
                         MMA_SMEM_U32 * 4);
    cudaFuncSetAttribute(gin_node0, cudaFuncAttributeMaxDynamicSharedMemorySize,
                         NODE0_SMEM_FLOATS * 4);

    int nodeGrid = (N + 127) / 128;
    int edgeGrid = (E + 255) / 256;
    int nScan = N + 1;
    int nb = (nScan + 511) / 512;

    // ----- CSR build -----
    cudaMemsetAsync(deg, 0, (size_t)nScan * sizeof(int));
    deg_count<<<edgeGrid, 256>>>(ei, E, deg);
    chunk_sum<<<nb, 512>>>(deg, nScan, bsum);
    scan_bsum<<<1, 1024>>>(bsum, nb);
    chunk_scan<<<nb, 512>>>(deg, nScan, bsum, off, pos);
    csr_scatter<<<edgeGrid, 256>>>(ei, E, pos, csr);

    // ----- layer 0 (scalar input) -----
    csr_agg1<<<(N + 255) / 256, 256>>>(off, csr, x, z, N);
    gin_node0<<<nodeGrid, 128, NODE0_SMEM_FLOATS * 4>>>(
        x, z, hh, eps, W1f,
        b1, g1, be1, m1, v1,
        W2, b2, g2, be2, m2, v2, N);

    // ----- layers 1..7: bf16 gather -> fp32 z -> bf16x2 MMA MLP -> bf16 hout -----
    for (int i = 1; i < LL; ++i) {
        const __nv_bfloat162* hprev = hh + (size_t)(i - 1) * lstride;
        __nv_bfloat162* hout = hh + (size_t)i * lstride;
        csr_agg_h<<<((size_t)N * 8 + 255) / 256, 256>>>(off, csr, hprev, z, eps + i, N);
        gin_node_mma<<<nodeGrid, 128, MMA_SMEM_U32 * 4>>>(
            z, hout,
            W1r + (size_t)(i - 1) * 4096, b1 + i * 64,
            g1 + i * 64, be1 + i * 64, m1 + i * 64, v1 + i * 64,
            W2 + (size_t)i * 4096, b2 + i * 64,
            g2 + i * 64, be2 + i * 64, m2 + i * 64, v2 + i * 64, N);
    }

    // ----- fused pool + head -----
    pool_classify<<<G, 128>>>(hh, lstride, batch, N, lw1, lb1, lw2, lb2, (float*)d_out);
}

// round 11
// speedup vs baseline: 1.0184x; 1.0184x over previous
#include <cuda_runtime.h>
#include <cuda_bf16.h>
#include <math.h>

#define MAXN 100000
#define MAXE 1600000
#define MAXG 500
#define LL 8
#define BN_EPS 1e-5f

// ---------------- device scratch ----------------
__device__ __nv_bfloat162 g_hh[2][(size_t)MAXN * 32];  // bf16 features, ping-pong (128B rows)
__device__ float g_z[(size_t)MAXN * 64];                // z = (1+eps)*h + agg (fp32)
__device__ float g_pooled[(size_t)MAXG * LL * 64];
__device__ int g_deg[MAXN + 1];
__device__ int g_off[MAXN + 2];
__device__ int g_pos[MAXN + 1];
__device__ int g_csr[MAXE];
__device__ int g_bsum[1024];

// ---------------- helpers ----------------
__device__ __forceinline__ unsigned long long pack2(float a, float b) {
    unsigned long long r;
    asm("mov.b64 %0, {%1, %2};" : "=l"(r) : "f"(a), "f"(b));
    return r;
}
__device__ __forceinline__ void unpack2(unsigned long long v, float& a, float& b) {
    asm("mov.b64 {%0, %1}, %2;" : "=f"(a), "=f"(b) : "l"(v));
}
__device__ __forceinline__ void fma2(unsigned long long& acc, unsigned long long a, unsigned long long b) {
    asm("fma.rn.f32x2 %0, %1, %2, %0;" : "+l"(acc) : "l"(a), "l"(b));
}
__device__ __forceinline__ void red4(float4* p, float4 v) {
    asm volatile("red.global.add.v4.f32 [%0], {%1, %2, %3, %4};"
                 :: "l"(p), "f"(v.x), "f"(v.y), "f"(v.z), "f"(v.w) : "memory");
}
// split (x,y) into bf16 hi pair + bf16 lo (residual) pair
__device__ __forceinline__ void bfsplit(float x, float y, unsigned& hi, unsigned& lo) {
    __nv_bfloat162 h = __floats2bfloat162_rn(x, y);
    float rx = x - __bfloat162float(h.x);
    float ry = y - __bfloat162float(h.y);
    __nv_bfloat162 l = __floats2bfloat162_rn(rx, ry);
    hi = *reinterpret_cast<unsigned*>(&h);
    lo = *reinterpret_cast<unsigned*>(&l);
}
__device__ __forceinline__ void mma16(float (&c)[4], unsigned a0, unsigned a1, unsigned a2, unsigned a3,
                                      unsigned b0, unsigned b1) {
    asm volatile("mma.sync.aligned.m16n8k16.row.col.f32.bf16.bf16.f32 "
                 "{%0,%1,%2,%3},{%4,%5,%6,%7},{%8,%9},{%0,%1,%2,%3};"
                 : "+f"(c[0]), "+f"(c[1]), "+f"(c[2]), "+f"(c[3])
                 : "r"(a0), "r"(a1), "r"(a2), "r"(a3), "r"(b0), "r"(b1));
}

// ============ CSR build ============
__global__ __launch_bounds__(256) void deg_count(const int* __restrict__ ei, int E, int* __restrict__ deg) {
    int e = blockIdx.x * 256 + threadIdx.x;
    if (e >= E) return;
    atomicAdd(&deg[ei[E + e]], 1);
}

__global__ __launch_bounds__(512) void chunk_sum(const int* __restrict__ deg, int n, int* __restrict__ bsum) {
    __shared__ int sh[512];
    int t = threadIdx.x;
    int i = blockIdx.x * 512 + t;
    sh[t] = (i < n) ? deg[i] : 0;
    __syncthreads();
#pragma unroll
    for (int s = 256; s > 0; s >>= 1) {
        if (t < s) sh[t] += sh[t + s];
        __syncthreads();
    }
    if (t == 0) bsum[blockIdx.x] = sh[0];
}

__global__ __launch_bounds__(1024) void scan_bsum(int* __restrict__ bsum, int nb) {
    __shared__ int sh[1024];
    int t = threadIdx.x;
    int v = (t < nb) ? bsum[t] : 0;
    sh[t] = v;
    __syncthreads();
    for (int d = 1; d < 1024; d <<= 1) {
        int add = (t >= d) ? sh[t - d] : 0;
        __syncthreads();
        sh[t] += add;
        __syncthreads();
    }
    if (t < nb) bsum[t] = sh[t] - v;   // exclusive
}

__global__ __launch_bounds__(512) void chunk_scan(const int* __restrict__ deg, int n,
                                                  const int* __restrict__ bsum,
                                                  int* __restrict__ off, int* __restrict__ pos) {
    __shared__ int sh[512];
    int t = threadIdx.x;
    int i = blockIdx.x * 512 + t;
    int v = (i < n) ? deg[i] : 0;
    sh[t] = v;
    __syncthreads();
    for (int d = 1; d < 512; d <<= 1) {
        int add = (t >= d) ? sh[t - d] : 0;
        __syncthreads();
        sh[t] += add;
        __syncthreads();
    }
    if (i < n) {
        int ex = sh[t] - v + bsum[blockIdx.x];
        off[i] = ex;
        pos[i] = ex;
    }
}

__global__ __launch_bounds__(256) void csr_scatter(const int* __restrict__ ei, int E,
                                                   int* __restrict__ pos, int* __restrict__ csr) {
    int e = blockIdx.x * 256 + threadIdx.x;
    if (e >= E) return;
    int src = ei[e];
    int dst = ei[E + e];
    int p = atomicAdd(&pos[dst], 1);
    csr[p] = src;
}

// ============ CSR aggregation (bf16 rows -> fp32 z) ============
__device__ __forceinline__ void addrow(float4 v, float* acc) {
    const __nv_bfloat162* h = reinterpret_cast<const __nv_bfloat162*>(&v);
#pragma unroll
    for (int j = 0; j < 4; ++j) {
        float2 f = __bfloat1622float2(h[j]);
        acc[2 * j]     += f.x;
        acc[2 * j + 1] += f.y;
    }
}

// 8 threads per node, each thread covers 8 contiguous features (16B).
__global__ __launch_bounds__(256) void csr_agg_h(const int* __restrict__ off, const int* __restrict__ csr,
                                                 const __nv_bfloat162* __restrict__ hh, float* __restrict__ z,
                                                 const float* __restrict__ eps, int N) {
    int t = blockIdx.x * 256 + threadIdx.x;
    int n = t >> 3;
    if (n >= N) return;
    int q = t & 7;
    const float4* hq = reinterpret_cast<const float4*>(hh) + q;
    float acc[8];
#pragma unroll
    for (int j = 0; j < 8; ++j) acc[j] = 0.f;
    int b = off[n], e = off[n + 1];
    int i = b;
    for (; i + 8 <= e; i += 8) {
        int idx[8];
#pragma unroll
        for (int u = 0; u < 8; ++u) idx[u] = __ldg(&csr[i + u]);
        float4 v[8];
#pragma unroll
        for (int u = 0; u < 8; ++u) v[u] = hq[idx[u] * 8];
#pragma unroll
        for (int u = 0; u < 8; ++u) addrow(v[u], acc);
    }
    for (; i + 4 <= e; i += 4) {
        int i0 = __ldg(&csr[i]);
        int i1 = __ldg(&csr[i + 1]);
        int i2 = __ldg(&csr[i + 2]);
        int i3 = __ldg(&csr[i + 3]);
        float4 v0 = hq[i0 * 8];
        float4 v1 = hq[i1 * 8];
        float4 v2 = hq[i2 * 8];
        float4 v3 = hq[i3 * 8];
        addrow(v0, acc);
        addrow(v1, acc);
        addrow(v2, acc);
        addrow(v3, acc);
    }
    for (; i < e; ++i) addrow(hq[__ldg(&csr[i]) * 8], acc);

    float ev = 1.0f + eps[0];
    float4 sv = hq[n * 8];
    const __nv_bfloat162* sh2 = reinterpret_cast<const __nv_bfloat162*>(&sv);
    float4 o0, o1;
    {
        float2 f0 = __bfloat1622float2(sh2[0]);
        float2 f1 = __bfloat1622float2(sh2[1]);
        float2 f2 = __bfloat1622float2(sh2[2]);
        float2 f3 = __bfloat1622float2(sh2[3]);
        o0.x = fmaf(ev, f0.x, acc[0]);
        o0.y = fmaf(ev, f0.y, acc[1]);
        o0.z = fmaf(ev, f1.x, acc[2]);
        o0.w = fmaf(ev, f1.y, acc[3]);
        o1.x = fmaf(ev, f2.x, acc[4]);
        o1.y = fmaf(ev, f2.y, acc[5]);
        o1.z = fmaf(ev, f3.x, acc[6]);
        o1.w = fmaf(ev, f3.y, acc[7]);
    }
    float4* zp = reinterpret_cast<float4*>(z + (size_t)n * 64 + q * 8);
    zp[0] = o0;
    zp[1] = o1;
}

// scalar features (layer 0)
__global__ __launch_bounds__(256) void csr_agg1(const int* __restrict__ off, const int* __restrict__ csr,
                                                const float* __restrict__ x, float* __restrict__ agg, int N) {
    int n = blockIdx.x * 256 + threadIdx.x;
    if (n >= N) return;
    int b = off[n], e = off[n + 1];
    float s = 0.f;
    int i = b;
    for (; i + 4 <= e; i += 4) {
        float v0 = x[__ldg(&csr[i])];
        float v1 = x[__ldg(&csr[i + 1])];
        float v2 = x[__ldg(&csr[i + 2])];
        float v3 = x[__ldg(&csr[i + 3])];
        s += (v0 + v1) + (v2 + v3);
    }
    for (; i < e; ++i) s += x[__ldg(&csr[i])];
    agg[n] = s;
}

// ============ BN params ============
__device__ __forceinline__ void load_bn_params(float* prm, int tid,
        const float* b1, const float* g1, const float* be1, const float* m1, const float* v1,
        const float* b2, const float* g2, const float* be2, const float* m2, const float* v2) {
    if (tid < 64) {
        float s1 = g1[tid] * rsqrtf(v1[tid] + BN_EPS);
        prm[tid]       = b1[tid];
        prm[64 + tid]  = s1;
        prm[128 + tid] = fmaf(-m1[tid], s1, be1[tid]);
        float s2 = g2[tid] * rsqrtf(v2[tid] + BN_EPS);
        prm[192 + tid] = b2[tid];
        prm[256 + tid] = s2;
        prm[320 + tid] = fmaf(-m2[tid], s2, be2[tid]);
    }
}

// ============ tensor-core node MLP (layers 1..7), bf16x2 split 3-term ============
#define AS 36   // row pitch in u32 (32 data + 4 pad)
#define OFF_W1HI 0
#define OFF_W1LO 2304
#define OFF_W2HI 4608
#define OFF_W2LO 6912
#define OFF_ZHI  9216
#define OFF_ZLO  13824
#define OFF_PRM  18432
#define MMA_SMEM_U32 (18432 + 384)

__device__ __forceinline__ void warp_gemm_bf(const unsigned* __restrict__ Whi,
                                             const unsigned* __restrict__ Wlo,
                                             const unsigned* __restrict__ zhi,
                                             const unsigned* __restrict__ zlo,
                                             int warp, int lane, float acc[2][8][4]) {
    int tig = lane & 3;
    int grp = lane >> 2;
#pragma unroll
    for (int kk = 0; kk < 4; ++kk) {
        int k2a = kk * 8 + tig;
        int k2b = kk * 8 + 4 + tig;
        unsigned bh[8][2], bl[8][2];
#pragma unroll
        for (int nt = 0; nt < 8; ++nt) {
            int n = nt * 8 + grp;
            bh[nt][0] = Whi[n * AS + k2a];
            bh[nt][1] = Whi[n * AS + k2b];
            bl[nt][0] = Wlo[n * AS + k2a];
            bl[nt][1] = Wlo[n * AS + k2b];
        }
#pragma unroll
        for (int mt = 0; mt < 2; ++mt) {
            int r0 = warp * 32 + mt * 16 + grp;
            unsigned ah0 = zhi[r0 * AS + k2a];
            unsigned ah1 = zhi[(r0 + 8) * AS + k2a];
            unsigned ah2 = zhi[r0 * AS + k2b];
            unsigned ah3 = zhi[(r0 + 8) * AS + k2b];
            unsigned al0 = zlo[r0 * AS + k2a];
            unsigned al1 = zlo[(r0 + 8) * AS + k2a];
            unsigned al2 = zlo[r0 * AS + k2b];
            unsigned al3 = zlo[(r0 + 8) * AS + k2b];
#pragma unroll
            for (int nt = 0; nt < 8; ++nt) {
                mma16(acc[mt][nt], ah0, ah1, ah2, ah3, bh[nt][0], bh[nt][1]);
                mma16(acc[mt][nt], ah0, ah1, ah2, ah3, bl[nt][0], bl[nt][1]);
                mma16(acc[mt][nt], al0, al1, al2, al3, bh[nt][0], bh[nt][1]);
            }
        }
    }
}

__global__ __launch_bounds__(128) void gin_node_mma(
        const float* __restrict__ zsrc,
        __nv_bfloat162* __restrict__ houth,
        const int* __restrict__ batch, float* __restrict__ pooled, int layer,
        const float* __restrict__ W1, const float* __restrict__ b1,
        const float* __restrict__ g1, const float* __restrict__ be1,
        const float* __restrict__ m1, const float* __restrict__ v1,
        const float* __restrict__ W2, const float* __restrict__ b2,
        const float* __restrict__ g2, const float* __restrict__ be2,
        const float* __restrict__ m2, const float* __restrict__ v2, int N) {
    extern __shared__ unsigned smu[];
    unsigned* W1hi = smu + OFF_W1HI;
    unsigned* W1lo = smu + OFF_W1LO;
    unsigned* W2hi = smu + OFF_W2HI;
    unsigned* W2lo = smu + OFF_W2LO;
    unsigned* zhi  = smu + OFF_ZHI;
    unsigned* zlo  = smu + OFF_ZLO;
    float* prm = reinterpret_cast<float*>(smu + OFF_PRM);
    __shared__ int sh_b[128];
    int tid = threadIdx.x;
    int warp = tid >> 5, lane = tid & 31;
    int tig = lane & 3, grp = lane >> 2;

    // weights -> shared, transposed to [n][k2] bf16x2 pairs, hi+lo split
    for (int idx = tid; idx < 2048; idx += 128) {
        int n = idx >> 5, k2 = idx & 31;
        int koff = (k2 * 2) * 64 + n;
        unsigned hi, lo;
        bfsplit(W1[koff], W1[koff + 64], hi, lo);
        W1hi[n * AS + k2] = hi;
        W1lo[n * AS + k2] = lo;
        bfsplit(W2[koff], W2[koff + 64], hi, lo);
        W2hi[n * AS + k2] = hi;
        W2lo[n * AS + k2] = lo;
    }
    load_bn_params(prm, tid, b1, g1, be1, m1, v1, b2, g2, be2, m2, v2);

    int n0 = blockIdx.x * 128;
    sh_b[tid] = (n0 + tid < N) ? batch[n0 + tid] : -1;

    // per-warp zs fill: lane -> row (warp*32 + lane)
    {
        int row = warp * 32 + lane;
        int n = n0 + row;
        unsigned* zh = zhi + row * AS;
        unsigned* zl = zlo + row * AS;
        if (n < N) {
            const float4* zp = reinterpret_cast<const float4*>(zsrc) + (size_t)n * 16;
#pragma unroll
            for (int q = 0; q < 16; ++q) {
                float4 v = zp[q];
                unsigned hi, lo;
                bfsplit(v.x, v.y, hi, lo);
                zh[2 * q] = hi;
                zl[2 * q] = lo;
                bfsplit(v.z, v.w, hi, lo);
                zh[2 * q + 1] = hi;
                zl[2 * q + 1] = lo;
            }
        } else {
#pragma unroll
            for (int q = 0; q < 32; ++q) { zh[q] = 0; zl[q] = 0; }
        }
    }
    __syncthreads();

    float acc[2][8][4];
#pragma unroll
    for (int mt = 0; mt < 2; ++mt)
#pragma unroll
        for (int nt = 0; nt < 8; ++nt)
#pragma unroll
            for (int p = 0; p < 4; ++p) acc[mt][nt][p] = 0.f;

    warp_gemm_bf(W1hi, W1lo, zhi, zlo, warp, lane, acc);

    // BN1 + ReLU -> back into zs (warp-private rows), zero acc
#pragma unroll
    for (int nt = 0; nt < 8; ++nt) {
        int j = nt * 8 + 2 * tig;
        float b1a = prm[j],       b1b = prm[j + 1];
        float s1a = prm[64 + j],  s1b = prm[64 + j + 1];
        float t1a = prm[128 + j], t1b = prm[128 + j + 1];
        int k2 = nt * 4 + tig;
#pragma unroll
        for (int mt = 0; mt < 2; ++mt) {
            float* C = acc[mt][nt];
            int row = warp * 32 + mt * 16 + grp;
            float y0 = fmaf(fmaxf(C[0] + b1a, 0.f), s1a, t1a);
            float y1 = fmaf(fmaxf(C[1] + b1b, 0.f), s1b, t1b);
            float y2 = fmaf(fmaxf(C[2] + b1a, 0.f), s1a, t1a);
            float y3 = fmaf(fmaxf(C[3] + b1b, 0.f), s1b, t1b);
            unsigned hi, lo;
            bfsplit(y0, y1, hi, lo);
            zhi[row * AS + k2] = hi;
            zlo[row * AS + k2] = lo;
            bfsplit(y2, y3, hi, lo);
            zhi[(row + 8) * AS + k2] = hi;
            zlo[(row + 8) * AS + k2] = lo;
            C[0] = C[1] = C[2] = C[3] = 0.f;
        }
    }
    __syncwarp();

    warp_gemm_bf(W2hi, W2lo, zhi, zlo, warp, lane, acc);

    // warp-uniform graph check over this warp's 32 rows
    int gme = sh_b[warp * 32 + lane];
    int g0 = __shfl_sync(0xffffffffu, gme, 0);
    bool uni = __all_sync(0xffffffffu, gme == g0) && (g0 >= 0);

    // BN2 + bf16 store + pooled RED (scalar atomicAdd)
#pragma unroll
    for (int nt = 0; nt < 8; ++nt) {
        int j = nt * 8 + 2 * tig;
        float b2a = prm[192 + j], b2b = prm[192 + j + 1];
        float s2a = prm[256 + j], s2b = prm[256 + j + 1];
        float t2a = prm[320 + j], t2b = prm[320 + j + 1];
        int jc = j >> 1;
        float p0 = 0.f, p1 = 0.f;
#pragma unroll
        for (int mt = 0; mt < 2; ++mt) {
            float* C = acc[mt][nt];
            int row = warp * 32 + mt * 16 + grp;
            int n = n0 + row;
            if (n < N) {
                float o0 = fmaf(fmaxf(C[0] + b2a, 0.f), s2a, t2a);
                float o1 = fmaf(fmaxf(C[1] + b2b, 0.f), s2b, t2b);
                houth[(size_t)n * 32 + jc] = __floats2bfloat162_rn(o0, o1);
                if (uni) { p0 += o0; p1 += o1; }
                else {
                    float* pp = pooled + (size_t)sh_b[row] * 512 + layer * 64 + j;
                    atomicAdd(pp, o0);
                    atomicAdd(pp + 1, o1);
                }
            }
            if (n + 8 < N) {
                float o2 = fmaf(fmaxf(C[2] + b2a, 0.f), s2a, t2a);
                float o3 = fmaf(fmaxf(C[3] + b2b, 0.f), s2b, t2b);
                houth[(size_t)(n + 8) * 32 + jc] = __floats2bfloat162_rn(o2, o3);
                if (uni) { p0 += o2; p1 += o3; }
                else {
                    float* pp = pooled + (size_t)sh_b[row + 8] * 512 + layer * 64 + j;
                    atomicAdd(pp, o2);
                    atomicAdd(pp + 1, o3);
                }
            }
        }
        if (uni) {
            float* pp = pooled + (size_t)g0 * 512 + layer * 64 + j;
            atomicAdd(pp, p0);
            atomicAdd(pp + 1, p1);
        }
    }
}

// ============ layer 0 (scalar input, FFMA path) ============
#define NODE0_SMEM_FLOATS (4096 + 384 + 64 + 128 * 65)

__device__ __forceinline__ void gemm_tile(const float* __restrict__ Wsh,
                                          const float* __restrict__ zs,
                                          int r, int c, unsigned long long acc[8][4]) {
    const float* zbase = zs + r * 8 * 65;
    const float* wbase = Wsh + c * 8;
#pragma unroll 2
    for (int k = 0; k < 64; ++k) {
        unsigned long long zz[8];
#pragma unroll
        for (int i = 0; i < 8; ++i) {
            float z = zbase[i * 65 + k];
            zz[i] = pack2(z, z);
        }
        ulonglong2 wa = *reinterpret_cast<const ulonglong2*>(wbase + k * 64);
        ulonglong2 wb = *reinterpret_cast<const ulonglong2*>(wbase + k * 64 + 4);
#pragma unroll
        for (int i = 0; i < 8; ++i) {
            fma2(acc[i][0], zz[i], wa.x);
            fma2(acc[i][1], zz[i], wa.y);
            fma2(acc[i][2], zz[i], wb.x);
            fma2(acc[i][3], zz[i], wb.y);
        }
    }
}

__global__ __launch_bounds__(128) void gin_node0(
        const float* __restrict__ x, const float* __restrict__ agg,
        __nv_bfloat162* __restrict__ houth, const int* __restrict__ batch,
        float* __restrict__ pooled, const float* __restrict__ eps,
        const float* __restrict__ W1f, const float* __restrict__ b1,
        const float* __restrict__ g1, const float* __restrict__ be1,
        const float* __restrict__ m1, const float* __restrict__ v1,
        const float* __restrict__ W2, const float* __restrict__ b2,
        const float* __restrict__ g2, const float* __restrict__ be2,
        const float* __restrict__ m2, const float* __restrict__ v2, int N) {
    extern __shared__ float sm[];
    float* W2s = sm;
    float* prm = sm + 4096;
    float* w1f = sm + 4480;
    float* zs  = sm + 4544;
    __shared__ int sh_b[128];
    int tid = threadIdx.x;

    float4* w2d = reinterpret_cast<float4*>(W2s);
    const float4* w2g = reinterpret_cast<const float4*>(W2);
#pragma unroll
    for (int i = tid; i < 1024; i += 128) w2d[i] = w2g[i];
    if (tid < 64) w1f[tid] = W1f[tid];
    load_bn_params(prm, tid, b1, g1, be1, m1, v1, b2, g2, be2, m2, v2);
    __syncthreads();   // REQUIRED: w1f/prm/W2s written above, read below (R9/R10 bug)

    int n0 = blockIdx.x * 128;
    int n = n0 + tid;
    sh_b[tid] = (n < N) ? batch[n] : -1;
    float* zrow = zs + tid * 65;
    if (n < N) {
        float ev = 1.0f + eps[0];
        float z = fmaf(ev, x[n], agg[n]);
#pragma unroll
        for (int j = 0; j < 64; ++j) {
            float y = fmaxf(fmaf(z, w1f[j], prm[j]), 0.f);
            zrow[j] = fmaf(y, prm[64 + j], prm[128 + j]);
        }
    } else {
#pragma unroll
        for (int j = 0; j < 64; ++j) zrow[j] = 0.f;
    }
    __syncthreads();

    int r = tid >> 3, c = tid & 7;
    unsigned long long acc[8][4];
#pragma unroll
    for (int i = 0; i < 8; ++i)
#pragma unroll
        for (int p = 0; p < 4; ++p) acc[i][p] = 0ull;
    gemm_tile(W2s, zs, r, c, acc);

    float4 b2a = *reinterpret_cast<const float4*>(prm + 192 + c * 8);
    float4 b2b = *reinterpret_cast<const float4*>(prm + 192 + c * 8 + 4);
    float4 s2a = *reinterpret_cast<const float4*>(prm + 256 + c * 8);
    float4 s2b = *reinterpret_cast<const float4*>(prm + 256 + c * 8 + 4);
    float4 t2a = *reinterpret_cast<const float4*>(prm + 320 + c * 8);
    float4 t2b = *reinterpret_cast<const float4*>(prm + 320 + c * 8 + 4);

    int base = r * 8;
    int g0 = sh_b[base];
    bool uni = (n0 + base + 7 < N) && (g0 >= 0);
    if (uni) {
#pragma unroll
        for (int i = 1; i < 8; ++i) uni = uni && (sh_b[base + i] == g0);
    }
    float4 sa = make_float4(0.f, 0.f, 0.f, 0.f);
    float4 sb = make_float4(0.f, 0.f, 0.f, 0.f);

#pragma unroll
    for (int i = 0; i < 8; ++i) {
        int node = base + i;
        int nn = n0 + node;
        if (nn >= N) break;
        float f0, f1, f2, f3, f4, f5, f6, f7;
        unpack2(acc[i][0], f0, f1);
        unpack2(acc[i][1], f2, f3);
        unpack2(acc[i][2], f4, f5);
        unpack2(acc[i][3], f6, f7);
        float4 oa, ob;
        oa.x = fmaf(fmaxf(f0 + b2a.x, 0.f), s2a.x, t2a.x);
        oa.y = fmaf(fmaxf(f1 + b2a.y, 0.f), s2a.y, t2a.y);
        oa.z = fmaf(fmaxf(f2 + b2a.z, 0.f), s2a.z, t2a.z);
        oa.w = fmaf(fmaxf(f3 + b2a.w, 0.f), s2a.w, t2a.w);
        ob.x = fmaf(fmaxf(f4 + b2b.x, 0.f), s2b.x, t2b.x);
        ob.y = fmaf(fmaxf(f5 + b2b.y, 0.f), s2b.y, t2b.y);
        ob.z = fmaf(fmaxf(f6 + b2b.z, 0.f), s2b.z, t2b.z);
        ob.w = fmaf(fmaxf(f7 + b2b.w, 0.f), s2b.w, t2b.w);
        __nv_bfloat162 p0 = __floats2bfloat162_rn(oa.x, oa.y);
        __nv_bfloat162 p1 = __floats2bfloat162_rn(oa.z, oa.w);
        __nv_bfloat162 p2 = __floats2bfloat162_rn(ob.x, ob.y);
        __nv_bfloat162 p3 = __floats2bfloat162_rn(ob.z, ob.w);
        uint4 u;
        u.x = *reinterpret_cast<unsigned*>(&p0);
        u.y = *reinterpret_cast<unsigned*>(&p1);
        u.z = *reinterpret_cast<unsigned*>(&p2);
        u.w = *reinterpret_cast<unsigned*>(&p3);
        reinterpret_cast<uint4*>(houth)[(size_t)nn * 8 + c] = u;
        if (uni) {
            sa.x += oa.x; sa.y += oa.y; sa.z += oa.z; sa.w += oa.w;
            sb.x += ob.x; sb.y += ob.y; sb.z += ob.z; sb.w += ob.w;
        } else {
            int g = sh_b[node];
            float4* pp = reinterpret_cast<float4*>(pooled) + (size_t)g * 128 + c * 2;
            red4(pp, oa);
            red4(pp + 1, ob);
        }
    }
    if (uni) {
        float4* pp = reinterpret_cast<float4*>(pooled) + (size_t)g0 * 128 + c * 2;
        red4(pp, sa);
        red4(pp + 1, sb);
    }
}

// ---------------- classifier head ----------------
__device__ __forceinline__ int lbound(const int* __restrict__ a, int n, int v) {
    int lo = 0, hi = n;
    while (lo < hi) {
        int mid = (lo + hi) >> 1;
        if (a[mid] < v) lo = mid + 1; else hi = mid;
    }
    return lo;
}

__global__ __launch_bounds__(64) void classify_kernel(
        const float* __restrict__ pooled, const int* __restrict__ batch, int N,
        const float* __restrict__ lw1, const float* __restrict__ lb1,
        const float* __restrict__ lw2, const float* __restrict__ lb2,
        float* __restrict__ out) {
    __shared__ float ps[512];
    __shared__ float hid[64];
    __shared__ float lg[3];
    __shared__ float inv;
    int g = blockIdx.x;
    int tid = threadIdx.x;
    if (tid == 0) {
        int a = lbound(batch, N, g);
        int b = lbound(batch, N, g + 1);
        int c = b - a;
        inv = 1.0f / (float)(c > 1 ? c : 1);
    }
    __syncthreads();
    for (int k = tid; k < 512; k += 64) ps[k] = pooled[(size_t)g * 512 + k] * inv;
    __syncthreads();
    float acc = lb1[tid];
#pragma unroll 8
    for (int k = 0; k < 512; ++k) acc = fmaf(ps[k], lw1[k * 64 + tid], acc);
    hid[tid] = fmaxf(acc, 0.f);
    __syncthreads();
    if (tid < 3) {
        float s = lb2[tid];
#pragma unroll
        for (int j = 0; j < 64; ++j) s = fmaf(hid[j], lw2[j * 3 + tid], s);
        lg[tid] = s;
    }
    __syncthreads();
    if (tid == 0) {
        float m = fmaxf(lg[0], fmaxf(lg[1], lg[2]));
        float e = expf(lg[0] - m) + expf(lg[1] - m) + expf(lg[2] - m);
        float lse = m + logf(e);
        out[g * 3 + 0] = lg[0] - lse;
        out[g * 3 + 1] = lg[1] - lse;
        out[g * 3 + 2] = lg[2] - lse;
    }
}

// ---------------- launcher ----------------
extern "C" void kernel_launch(void* const* d_in, const int* in_sizes, int n_in,
                              void* d_out, int out_size) {
    const float* x     = (const float*)d_in[0];
    const int*   ei    = (const int*)d_in[1];
    const int*   batch = (const int*)d_in[2];
    int bi = (in_sizes[3] == 1) ? 4 : 3;
    const float* eps  = (const float*)d_in[bi + 0];
    const float* W1f  = (const float*)d_in[bi + 1];
    const float* W1r  = (const float*)d_in[bi + 2];
    const float* b1   = (const float*)d_in[bi + 3];
    const float* g1   = (const float*)d_in[bi + 4];
    const float* be1  = (const float*)d_in[bi + 5];
    const float* m1   = (const float*)d_in[bi + 6];
    const float* v1   = (const float*)d_in[bi + 7];
    const float* W2   = (const float*)d_in[bi + 8];
    const float* b2   = (const float*)d_in[bi + 9];
    const float* g2   = (const float*)d_in[bi + 10];
    const float* be2  = (const float*)d_in[bi + 11];
    const float* m2   = (const float*)d_in[bi + 12];
    const float* v2   = (const float*)d_in[bi + 13];
    const float* lw1  = (const float*)d_in[bi + 14];
    const float* lb1  = (const float*)d_in[bi + 15];
    const float* lw2  = (const float*)d_in[bi + 16];
    const float* lb2  = (const float*)d_in[bi + 17];

    int N = in_sizes[0];
    int E = in_sizes[1] / 2;
    int G = out_size / 3;
    if (N > MAXN) N = MAXN;
    if (E > MAXE) E = MAXE;
    if (G > MAXG) G = MAXG;

    __nv_bfloat162 *hh0, *hh1;
    float *z, *pooled;
    int *deg, *off, *pos, *csr, *bsum;
    cudaGetSymbolAddress((void**)&hh0, g_hh);
    hh1 = hh0 + (size_t)MAXN * 32;
    cudaGetSymbolAddress((void**)&z, g_z);
    cudaGetSymbolAddress((void**)&pooled, g_pooled);
    cudaGetSymbolAddress((void**)&deg, g_deg);
    cudaGetSymbolAddress((void**)&off, g_off);
    cudaGetSymbolAddress((void**)&pos, g_pos);
    cudaGetSymbolAddress((void**)&csr, g_csr);
    cudaGetSymbolAddress((void**)&bsum, g_bsum);

    cudaFuncSetAttribute(gin_node_mma, cudaFuncAttributeMaxDynamicSharedMemorySize,
                         MMA_SMEM_U32 * 4);
    cudaFuncSetAttribute(gin_node0, cudaFuncAttributeMaxDynamicSharedMemorySize,
                         NODE0_SMEM_FLOATS * 4);

    int nodeGrid = (N + 127) / 128;
    int edgeGrid = (E + 255) / 256;
    int nScan = N + 1;
    int nb = (nScan + 511) / 512;

    // ----- CSR build + pooled clear -----
    cudaMemsetAsync(deg, 0, (size_t)nScan * sizeof(int));
    cudaMemsetAsync(pooled, 0, (size_t)G * 512 * sizeof(float));
    deg_count<<<edgeGrid, 256>>>(ei, E, deg);
    chunk_sum<<<nb, 512>>>(deg, nScan, bsum);
    scan_bsum<<<1, 1024>>>(bsum, nb);
    chunk_scan<<<nb, 512>>>(deg, nScan, bsum, off, pos);
    csr_scatter<<<edgeGrid, 256>>>(ei, E, pos, csr);

    // ----- layer 0 (scalar input) -----
    csr_agg1<<<(N + 255) / 256, 256>>>(off, csr, x, z, N);
    gin_node0<<<nodeGrid, 128, NODE0_SMEM_FLOATS * 4>>>(
        x, z, hh0, batch, pooled, eps, W1f,
        b1, g1, be1, m1, v1,
        W2, b2, g2, be2, m2, v2, N);

    // ----- layers 1..7: bf16 gather -> fp32 z -> bf16x2 MMA MLP (+atomic pool) -----
    for (int i = 1; i < LL; ++i) {
        const __nv_bfloat162* hprev = (i & 1) ? hh0 : hh1;
        __nv_bfloat162* hout = (i & 1) ? hh1 : hh0;
        csr_agg_h<<<((size_t)N * 8 + 255) / 256, 256>>>(off, csr, hprev, z, eps + i, N);
        gin_node_mma<<<nodeGrid, 128, MMA_SMEM_U32 * 4>>>(
            z, hout, batch, pooled, i,
            W1r + (size_t)(i - 1) * 4096, b1 + i * 64,
            g1 + i * 64, be1 + i * 64, m1 + i * 64, v1 + i * 64,
            W2 + (size_t)i * 4096, b2 + i * 64,
            g2 + i * 64, be2 + i * 64, m2 + i * 64, v2 + i * 64, N);
    }

    // ----- head -----
    classify_kernel<<<G, 64>>>(pooled, batch, N, lw1, lb1, lw2, lb2, (float*)d_out);
}

// round 12
// speedup vs baseline: 1.3147x; 1.2909x over previous
#include <cuda_runtime.h>
#include <cuda_bf16.h>
#include <math.h>

#define MAXN 100000
#define MAXE 1600000
#define MAXG 500
#define LL 8
#define BN_EPS 1e-5f

// ---------------- device scratch ----------------
__device__ __nv_bfloat162 g_hh[2][(size_t)MAXN * 32];  // bf16 features, ping-pong (128B rows)
__device__ float g_z[(size_t)MAXN * 64];                // z = (1+eps)*h + agg (fp32)
__device__ float g_pooled[(size_t)MAXG * LL * 64];
__device__ unsigned g_wprep[7 * 9216];                  // split-transposed weights, smem layout
__device__ int g_deg[MAXN + 1];
__device__ int g_off[MAXN + 2];
__device__ int g_pos[MAXN + 1];
__device__ int g_csr[MAXE];
__device__ int g_bsum[1024];

// ---------------- helpers ----------------
__device__ __forceinline__ unsigned long long pack2(float a, float b) {
    unsigned long long r;
    asm("mov.b64 %0, {%1, %2};" : "=l"(r) : "f"(a), "f"(b));
    return r;
}
__device__ __forceinline__ void unpack2(unsigned long long v, float& a, float& b) {
    asm("mov.b64 {%0, %1}, %2;" : "=f"(a), "=f"(b) : "l"(v));
}
__device__ __forceinline__ void fma2(unsigned long long& acc, unsigned long long a, unsigned long long b) {
    asm("fma.rn.f32x2 %0, %1, %2, %0;" : "+l"(acc) : "l"(a), "l"(b));
}
__device__ __forceinline__ void red4(float4* p, float4 v) {
    asm volatile("red.global.add.v4.f32 [%0], {%1, %2, %3, %4};"
                 :: "l"(p), "f"(v.x), "f"(v.y), "f"(v.z), "f"(v.w) : "memory");
}
// split (x,y) into bf16 hi pair + bf16 lo (residual) pair
__device__ __forceinline__ void bfsplit(float x, float y, unsigned& hi, unsigned& lo) {
    __nv_bfloat162 h = __floats2bfloat162_rn(x, y);
    float rx = x - __bfloat162float(h.x);
    float ry = y - __bfloat162float(h.y);
    __nv_bfloat162 l = __floats2bfloat162_rn(rx, ry);
    hi = *reinterpret_cast<unsigned*>(&h);
    lo = *reinterpret_cast<unsigned*>(&l);
}
__device__ __forceinline__ void mma16(float (&c)[4], unsigned a0, unsigned a1, unsigned a2, unsigned a3,
                                      unsigned b0, unsigned b1) {
    asm volatile("mma.sync.aligned.m16n8k16.row.col.f32.bf16.bf16.f32 "
                 "{%0,%1,%2,%3},{%4,%5,%6,%7},{%8,%9},{%0,%1,%2,%3};"
                 : "+f"(c[0]), "+f"(c[1]), "+f"(c[2]), "+f"(c[3])
                 : "r"(a0), "r"(a1), "r"(a2), "r"(a3), "r"(b0), "r"(b1));
}

// ============ CSR build ============
__global__ __launch_bounds__(256) void deg_count(const int* __restrict__ ei, int E, int* __restrict__ deg) {
    int e = blockIdx.x * 256 + threadIdx.x;
    if (e >= E) return;
    atomicAdd(&deg[ei[E + e]], 1);
}

__global__ __launch_bounds__(512) void chunk_sum(const int* __restrict__ deg, int n, int* __restrict__ bsum) {
    __shared__ int sh[512];
    int t = threadIdx.x;
    int i = blockIdx.x * 512 + t;
    sh[t] = (i < n) ? deg[i] : 0;
    __syncthreads();
#pragma unroll
    for (int s = 256; s > 0; s >>= 1) {
        if (t < s) sh[t] += sh[t + s];
        __syncthreads();
    }
    if (t == 0) bsum[blockIdx.x] = sh[0];
}

__global__ __launch_bounds__(1024) void scan_bsum(int* __restrict__ bsum, int nb) {
    __shared__ int sh[1024];
    int t = threadIdx.x;
    int v = (t < nb) ? bsum[t] : 0;
    sh[t] = v;
    __syncthreads();
    for (int d = 1; d < 1024; d <<= 1) {
        int add = (t >= d) ? sh[t - d] : 0;
        __syncthreads();
        sh[t] += add;
        __syncthreads();
    }
    if (t < nb) bsum[t] = sh[t] - v;   // exclusive
}

__global__ __launch_bounds__(512) void chunk_scan(const int* __restrict__ deg, int n,
                                                  const int* __restrict__ bsum,
                                                  int* __restrict__ off, int* __restrict__ pos) {
    __shared__ int sh[512];
    int t = threadIdx.x;
    int i = blockIdx.x * 512 + t;
    int v = (i < n) ? deg[i] : 0;
    sh[t] = v;
    __syncthreads();
    for (int d = 1; d < 512; d <<= 1) {
        int add = (t >= d) ? sh[t - d] : 0;
        __syncthreads();
        sh[t] += add;
        __syncthreads();
    }
    if (i < n) {
        int ex = sh[t] - v + bsum[blockIdx.x];
        off[i] = ex;
        pos[i] = ex;
    }
}

__global__ __launch_bounds__(256) void csr_scatter(const int* __restrict__ ei, int E,
                                                   int* __restrict__ pos, int* __restrict__ csr) {
    int e = blockIdx.x * 256 + threadIdx.x;
    if (e >= E) return;
    int src = ei[e];
    int dst = ei[E + e];
    int p = atomicAdd(&pos[dst], 1);
    csr[p] = src;
}

// ============ weight pre-transform (once per launch) ============
#define AS 36   // row pitch in u32 (32 data + 4 pad)

__global__ __launch_bounds__(128) void prep_weights(const float* __restrict__ W1r,
                                                    const float* __restrict__ W2all,
                                                    unsigned* __restrict__ wprep) {
    int layer = blockIdx.x;                    // 0..6 -> layers 1..7
    const float* W1 = W1r + (size_t)layer * 4096;
    const float* W2 = W2all + (size_t)(layer + 1) * 4096;
    unsigned* dst = wprep + (size_t)layer * 9216;
    for (int idx = threadIdx.x; idx < 2048; idx += 128) {
        int n = idx >> 5, k2 = idx & 31;
        int koff = k2 * 128 + n;
        unsigned hi, lo;
        bfsplit(W1[koff], W1[koff + 64], hi, lo);
        dst[n * AS + k2] = hi;
        dst[2304 + n * AS + k2] = lo;
        bfsplit(W2[koff], W2[koff + 64], hi, lo);
        dst[4608 + n * AS + k2] = hi;
        dst[6912 + n * AS + k2] = lo;
    }
}

// ============ CSR aggregation (bf16 rows -> fp32 z) ============
__device__ __forceinline__ void addrow(float4 v, float* acc) {
    const __nv_bfloat162* h = reinterpret_cast<const __nv_bfloat162*>(&v);
#pragma unroll
    for (int j = 0; j < 4; ++j) {
        float2 f = __bfloat1622float2(h[j]);
        acc[2 * j]     += f.x;
        acc[2 * j + 1] += f.y;
    }
}

// 8 threads per node, each thread covers 8 contiguous features (16B).
__global__ __launch_bounds__(256) void csr_agg_h(const int* __restrict__ off, const int* __restrict__ csr,
                                                 const __nv_bfloat162* __restrict__ hh, float* __restrict__ z,
                                                 const float* __restrict__ eps, int N) {
    int t = blockIdx.x * 256 + threadIdx.x;
    int n = t >> 3;
    if (n >= N) return;
    int q = t & 7;
    const float4* hq = reinterpret_cast<const float4*>(hh) + q;
    float acc[8];
#pragma unroll
    for (int j = 0; j < 8; ++j) acc[j] = 0.f;
    int b = off[n], e = off[n + 1];
    int i = b;
    for (; i + 8 <= e; i += 8) {
        int idx[8];
#pragma unroll
        for (int u = 0; u < 8; ++u) idx[u] = __ldg(&csr[i + u]);
        float4 v[8];
#pragma unroll
        for (int u = 0; u < 8; ++u) v[u] = hq[idx[u] * 8];
#pragma unroll
        for (int u = 0; u < 8; ++u) addrow(v[u], acc);
    }
    for (; i + 4 <= e; i += 4) {
        int i0 = __ldg(&csr[i]);
        int i1 = __ldg(&csr[i + 1]);
        int i2 = __ldg(&csr[i + 2]);
        int i3 = __ldg(&csr[i + 3]);
        float4 v0 = hq[i0 * 8];
        float4 v1 = hq[i1 * 8];
        float4 v2 = hq[i2 * 8];
        float4 v3 = hq[i3 * 8];
        addrow(v0, acc);
        addrow(v1, acc);
        addrow(v2, acc);
        addrow(v3, acc);
    }
    for (; i < e; ++i) addrow(hq[__ldg(&csr[i]) * 8], acc);

    float ev = 1.0f + eps[0];
    float4 sv = hq[n * 8];
    const __nv_bfloat162* sh2 = reinterpret_cast<const __nv_bfloat162*>(&sv);
    float4 o0, o1;
    {
        float2 f0 = __bfloat1622float2(sh2[0]);
        float2 f1 = __bfloat1622float2(sh2[1]);
        float2 f2 = __bfloat1622float2(sh2[2]);
        float2 f3 = __bfloat1622float2(sh2[3]);
        o0.x = fmaf(ev, f0.x, acc[0]);
        o0.y = fmaf(ev, f0.y, acc[1]);
        o0.z = fmaf(ev, f1.x, acc[2]);
        o0.w = fmaf(ev, f1.y, acc[3]);
        o1.x = fmaf(ev, f2.x, acc[4]);
        o1.y = fmaf(ev, f2.y, acc[5]);
        o1.z = fmaf(ev, f3.x, acc[6]);
        o1.w = fmaf(ev, f3.y, acc[7]);
    }
    float4* zp = reinterpret_cast<float4*>(z + (size_t)n * 64 + q * 8);
    zp[0] = o0;
    zp[1] = o1;
}

// scalar features (layer 0)
__global__ __launch_bounds__(256) void csr_agg1(const int* __restrict__ off, const int* __restrict__ csr,
                                                const float* __restrict__ x, float* __restrict__ agg, int N) {
    int n = blockIdx.x * 256 + threadIdx.x;
    if (n >= N) return;
    int b = off[n], e = off[n + 1];
    float s = 0.f;
    int i = b;
    for (; i + 4 <= e; i += 4) {
        float v0 = x[__ldg(&csr[i])];
        float v1 = x[__ldg(&csr[i + 1])];
        float v2 = x[__ldg(&csr[i + 2])];
        float v3 = x[__ldg(&csr[i + 3])];
        s += (v0 + v1) + (v2 + v3);
    }
    for (; i < e; ++i) s += x[__ldg(&csr[i])];
    agg[n] = s;
}

// ============ BN params ============
__device__ __forceinline__ void load_bn_params(float* prm, int tid,
        const float* b1, const float* g1, const float* be1, const float* m1, const float* v1,
        const float* b2, const float* g2, const float* be2, const float* m2, const float* v2) {
    if (tid < 64) {
        float s1 = g1[tid] * rsqrtf(v1[tid] + BN_EPS);
        prm[tid]       = b1[tid];
        prm[64 + tid]  = s1;
        prm[128 + tid] = fmaf(-m1[tid], s1, be1[tid]);
        float s2 = g2[tid] * rsqrtf(v2[tid] + BN_EPS);
        prm[192 + tid] = b2[tid];
        prm[256 + tid] = s2;
        prm[320 + tid] = fmaf(-m2[tid], s2, be2[tid]);
    }
}

// ============ tensor-core node MLP (layers 1..7), bf16x2 split 3-term ============
#define OFF_W1HI 0
#define OFF_W1LO 2304
#define OFF_W2HI 4608
#define OFF_W2LO 6912
#define OFF_ZHI  9216
#define OFF_ZLO  13824
#define OFF_PRM  18432
#define MMA_SMEM_U32 (18432 + 384)

__device__ __forceinline__ void warp_gemm_bf(const unsigned* __restrict__ Whi,
                                             const unsigned* __restrict__ Wlo,
                                             const unsigned* __restrict__ zhi,
                                             const unsigned* __restrict__ zlo,
                                             int warp, int lane, float acc[2][8][4]) {
    int tig = lane & 3;
    int grp = lane >> 2;
#pragma unroll
    for (int kk = 0; kk < 4; ++kk) {
        int k2a = kk * 8 + tig;
        int k2b = kk * 8 + 4 + tig;
        unsigned bh[8][2], bl[8][2];
#pragma unroll
        for (int nt = 0; nt < 8; ++nt) {
            int n = nt * 8 + grp;
            bh[nt][0] = Whi[n * AS + k2a];
            bh[nt][1] = Whi[n * AS + k2b];
            bl[nt][0] = Wlo[n * AS + k2a];
            bl[nt][1] = Wlo[n * AS + k2b];
        }
#pragma unroll
        for (int mt = 0; mt < 2; ++mt) {
            int r0 = warp * 32 + mt * 16 + grp;
            unsigned ah0 = zhi[r0 * AS + k2a];
            unsigned ah1 = zhi[(r0 + 8) * AS + k2a];
            unsigned ah2 = zhi[r0 * AS + k2b];
            unsigned ah3 = zhi[(r0 + 8) * AS + k2b];
            unsigned al0 = zlo[r0 * AS + k2a];
            unsigned al1 = zlo[(r0 + 8) * AS + k2a];
            unsigned al2 = zlo[r0 * AS + k2b];
            unsigned al3 = zlo[(r0 + 8) * AS + k2b];
#pragma unroll
            for (int nt = 0; nt < 8; ++nt) {
                mma16(acc[mt][nt], ah0, ah1, ah2, ah3, bh[nt][0], bh[nt][1]);
                mma16(acc[mt][nt], ah0, ah1, ah2, ah3, bl[nt][0], bl[nt][1]);
                mma16(acc[mt][nt], al0, al1, al2, al3, bh[nt][0], bh[nt][1]);
            }
        }
    }
}

__global__ __launch_bounds__(128) void gin_node_mma(
        const float* __restrict__ zsrc,
        __nv_bfloat162* __restrict__ houth,
        const int* __restrict__ batch, float* __restrict__ pooled, int layer,
        const unsigned* __restrict__ wprep,
        const float* __restrict__ b1,
        const float* __restrict__ g1, const float* __restrict__ be1,
        const float* __restrict__ m1, const float* __restrict__ v1,
        const float* __restrict__ b2,
        const float* __restrict__ g2, const float* __restrict__ be2,
        const float* __restrict__ m2, const float* __restrict__ v2, int N) {
    extern __shared__ unsigned smu[];
    unsigned* W1hi = smu + OFF_W1HI;
    unsigned* W1lo = smu + OFF_W1LO;
    unsigned* W2hi = smu + OFF_W2HI;
    unsigned* W2lo = smu + OFF_W2LO;
    unsigned* zhi  = smu + OFF_ZHI;
    unsigned* zlo  = smu + OFF_ZLO;
    float* prm = reinterpret_cast<float*>(smu + OFF_PRM);
    __shared__ int sh_b[128];
    int tid = threadIdx.x;
    int warp = tid >> 5, lane = tid & 31;
    int tig = lane & 3, grp = lane >> 2;

    // coalesced copy of pre-transposed weights (9216 u32 = 2304 uint4)
    {
        const uint4* wsrc = reinterpret_cast<const uint4*>(wprep);
        uint4* wdst = reinterpret_cast<uint4*>(smu);
#pragma unroll
        for (int i = tid; i < 2304; i += 128) wdst[i] = wsrc[i];
    }
    load_bn_params(prm, tid, b1, g1, be1, m1, v1, b2, g2, be2, m2, v2);

    int n0 = blockIdx.x * 128;
    sh_b[tid] = (n0 + tid < N) ? batch[n0 + tid] : -1;

    // coalesced z fill: (row, q) with q fastest -> contiguous 16B reads
    for (int idx = tid; idx < 2048; idx += 128) {
        int row = idx >> 4;
        int q = idx & 15;
        int n = n0 + row;
        unsigned hi0 = 0, lo0 = 0, hi1 = 0, lo1 = 0;
        if (n < N) {
            float4 v = reinterpret_cast<const float4*>(zsrc)[(size_t)n * 16 + q];
            bfsplit(v.x, v.y, hi0, lo0);
            bfsplit(v.z, v.w, hi1, lo1);
        }
        zhi[row * AS + 2 * q]     = hi0;
        zhi[row * AS + 2 * q + 1] = hi1;
        zlo[row * AS + 2 * q]     = lo0;
        zlo[row * AS + 2 * q + 1] = lo1;
    }
    __syncthreads();

    float acc[2][8][4];
#pragma unroll
    for (int mt = 0; mt < 2; ++mt)
#pragma unroll
        for (int nt = 0; nt < 8; ++nt)
#pragma unroll
            for (int p = 0; p < 4; ++p) acc[mt][nt][p] = 0.f;

    warp_gemm_bf(W1hi, W1lo, zhi, zlo, warp, lane, acc);

    // BN1 + ReLU -> back into zs (warp-private rows), zero acc
#pragma unroll
    for (int nt = 0; nt < 8; ++nt) {
        int j = nt * 8 + 2 * tig;
        float b1a = prm[j],       b1b = prm[j + 1];
        float s1a = prm[64 + j],  s1b = prm[64 + j + 1];
        float t1a = prm[128 + j], t1b = prm[128 + j + 1];
        int k2 = nt * 4 + tig;
#pragma unroll
        for (int mt = 0; mt < 2; ++mt) {
            float* C = acc[mt][nt];
            int row = warp * 32 + mt * 16 + grp;
            float y0 = fmaf(fmaxf(C[0] + b1a, 0.f), s1a, t1a);
            float y1 = fmaf(fmaxf(C[1] + b1b, 0.f), s1b, t1b);
            float y2 = fmaf(fmaxf(C[2] + b1a, 0.f), s1a, t1a);
            float y3 = fmaf(fmaxf(C[3] + b1b, 0.f), s1b, t1b);
            unsigned hi, lo;
            bfsplit(y0, y1, hi, lo);
            zhi[row * AS + k2] = hi;
            zlo[row * AS + k2] = lo;
            bfsplit(y2, y3, hi, lo);
            zhi[(row + 8) * AS + k2] = hi;
            zlo[(row + 8) * AS + k2] = lo;
            C[0] = C[1] = C[2] = C[3] = 0.f;
        }
    }
    __syncwarp();

    warp_gemm_bf(W2hi, W2lo, zhi, zlo, warp, lane, acc);

    // warp-uniform graph check over this warp's 32 rows
    int gme = sh_b[warp * 32 + lane];
    int g0 = __shfl_sync(0xffffffffu, gme, 0);
    bool uni = __all_sync(0xffffffffu, gme == g0) && (g0 >= 0);

    // BN2 + bf16 store + pooled RED (scalar atomicAdd)
#pragma unroll
    for (int nt = 0; nt < 8; ++nt) {
        int j = nt * 8 + 2 * tig;
        float b2a = prm[192 + j], b2b = prm[192 + j + 1];
        float s2a = prm[256 + j], s2b = prm[256 + j + 1];
        float t2a = prm[320 + j], t2b = prm[320 + j + 1];
        int jc = j >> 1;
        float p0 = 0.f, p1 = 0.f;
#pragma unroll
        for (int mt = 0; mt < 2; ++mt) {
            float* C = acc[mt][nt];
            int row = warp * 32 + mt * 16 + grp;
            int n = n0 + row;
            if (n < N) {
                float o0 = fmaf(fmaxf(C[0] + b2a, 0.f), s2a, t2a);
                float o1 = fmaf(fmaxf(C[1] + b2b, 0.f), s2b, t2b);
                houth[(size_t)n * 32 + jc] = __floats2bfloat162_rn(o0, o1);
                if (uni) { p0 += o0; p1 += o1; }
                else {
                    float* pp = pooled + (size_t)sh_b[row] * 512 + layer * 64 + j;
                    atomicAdd(pp, o0);
                    atomicAdd(pp + 1, o1);
                }
            }
            if (n + 8 < N) {
                float o2 = fmaf(fmaxf(C[2] + b2a, 0.f), s2a, t2a);
                float o3 = fmaf(fmaxf(C[3] + b2b, 0.f), s2b, t2b);
                houth[(size_t)(n + 8) * 32 + jc] = __floats2bfloat162_rn(o2, o3);
                if (uni) { p0 += o2; p1 += o3; }
                else {
                    float* pp = pooled + (size_t)sh_b[row + 8] * 512 + layer * 64 + j;
                    atomicAdd(pp, o2);
                    atomicAdd(pp + 1, o3);
                }
            }
        }
        if (uni) {
            float* pp = pooled + (size_t)g0 * 512 + layer * 64 + j;
            atomicAdd(pp, p0);
            atomicAdd(pp + 1, p1);
        }
    }
}

// ============ layer 0 (scalar input, FFMA path) ============
#define NODE0_SMEM_FLOATS (4096 + 384 + 64 + 128 * 65)

__device__ __forceinline__ void gemm_tile(const float* __restrict__ Wsh,
                                          const float* __restrict__ zs,
                                          int r, int c, unsigned long long acc[8][4]) {
    const float* zbase = zs + r * 8 * 65;
    const float* wbase = Wsh + c * 8;
#pragma unroll 2
    for (int k = 0; k < 64; ++k) {
        unsigned long long zz[8];
#pragma unroll
        for (int i = 0; i < 8; ++i) {
            float z = zbase[i * 65 + k];
            zz[i] = pack2(z, z);
        }
        ulonglong2 wa = *reinterpret_cast<const ulonglong2*>(wbase + k * 64);
        ulonglong2 wb = *reinterpret_cast<const ulonglong2*>(wbase + k * 64 + 4);
#pragma unroll
        for (int i = 0; i < 8; ++i) {
            fma2(acc[i][0], zz[i], wa.x);
            fma2(acc[i][1], zz[i], wa.y);
            fma2(acc[i][2], zz[i], wb.x);
            fma2(acc[i][3], zz[i], wb.y);
        }
    }
}

__global__ __launch_bounds__(128) void gin_node0(
        const float* __restrict__ x, const float* __restrict__ agg,
        __nv_bfloat162* __restrict__ houth, const int* __restrict__ batch,
        float* __restrict__ pooled, const float* __restrict__ eps,
        const float* __restrict__ W1f, const float* __restrict__ b1,
        const float* __restrict__ g1, const float* __restrict__ be1,
        const float* __restrict__ m1, const float* __restrict__ v1,
        const float* __restrict__ W2, const float* __restrict__ b2,
        const float* __restrict__ g2, const float* __restrict__ be2,
        const float* __restrict__ m2, const float* __restrict__ v2, int N) {
    extern __shared__ float sm[];
    float* W2s = sm;
    float* prm = sm + 4096;
    float* w1f = sm + 4480;
    float* zs  = sm + 4544;
    __shared__ int sh_b[128];
    int tid = threadIdx.x;

    float4* w2d = reinterpret_cast<float4*>(W2s);
    const float4* w2g = reinterpret_cast<const float4*>(W2);
#pragma unroll
    for (int i = tid; i < 1024; i += 128) w2d[i] = w2g[i];
    if (tid < 64) w1f[tid] = W1f[tid];
    load_bn_params(prm, tid, b1, g1, be1, m1, v1, b2, g2, be2, m2, v2);
    __syncthreads();   // w1f/prm/W2s written above, read below

    int n0 = blockIdx.x * 128;
    int n = n0 + tid;
    sh_b[tid] = (n < N) ? batch[n] : -1;
    float* zrow = zs + tid * 65;
    if (n < N) {
        float ev = 1.0f + eps[0];
        float z = fmaf(ev, x[n], agg[n]);
#pragma unroll
        for (int j = 0; j < 64; ++j) {
            float y = fmaxf(fmaf(z, w1f[j], prm[j]), 0.f);
            zrow[j] = fmaf(y, prm[64 + j], prm[128 + j]);
        }
    } else {
#pragma unroll
        for (int j = 0; j < 64; ++j) zrow[j] = 0.f;
    }
    __syncthreads();

    int r = tid >> 3, c = tid & 7;
    unsigned long long acc[8][4];
#pragma unroll
    for (int i = 0; i < 8; ++i)
#pragma unroll
        for (int p = 0; p < 4; ++p) acc[i][p] = 0ull;
    gemm_tile(W2s, zs, r, c, acc);

    float4 b2a = *reinterpret_cast<const float4*>(prm + 192 + c * 8);
    float4 b2b = *reinterpret_cast<const float4*>(prm + 192 + c * 8 + 4);
    float4 s2a = *reinterpret_cast<const float4*>(prm + 256 + c * 8);
    float4 s2b = *reinterpret_cast<const float4*>(prm + 256 + c * 8 + 4);
    float4 t2a = *reinterpret_cast<const float4*>(prm + 320 + c * 8);
    float4 t2b = *reinterpret_cast<const float4*>(prm + 320 + c * 8 + 4);

    int base = r * 8;
    int g0 = sh_b[base];
    bool uni = (n0 + base + 7 < N) && (g0 >= 0);
    if (uni) {
#pragma unroll
        for (int i = 1; i < 8; ++i) uni = uni && (sh_b[base + i] == g0);
    }
    float4 sa = make_float4(0.f, 0.f, 0.f, 0.f);
    float4 sb = make_float4(0.f, 0.f, 0.f, 0.f);

#pragma unroll
    for (int i = 0; i < 8; ++i) {
        int node = base + i;
        int nn = n0 + node;
        if (nn >= N) break;
        float f0, f1, f2, f3, f4, f5, f6, f7;
        unpack2(acc[i][0], f0, f1);
        unpack2(acc[i][1], f2, f3);
        unpack2(acc[i][2], f4, f5);
        unpack2(acc[i][3], f6, f7);
        float4 oa, ob;
        oa.x = fmaf(fmaxf(f0 + b2a.x, 0.f), s2a.x, t2a.x);
        oa.y = fmaf(fmaxf(f1 + b2a.y, 0.f), s2a.y, t2a.y);
        oa.z = fmaf(fmaxf(f2 + b2a.z, 0.f), s2a.z, t2a.z);
        oa.w = fmaf(fmaxf(f3 + b2a.w, 0.f), s2a.w, t2a.w);
        ob.x = fmaf(fmaxf(f4 + b2b.x, 0.f), s2b.x, t2b.x);
        ob.y = fmaf(fmaxf(f5 + b2b.y, 0.f), s2b.y, t2b.y);
        ob.z = fmaf(fmaxf(f6 + b2b.z, 0.f), s2b.z, t2b.z);
        ob.w = fmaf(fmaxf(f7 + b2b.w, 0.f), s2b.w, t2b.w);
        __nv_bfloat162 p0 = __floats2bfloat162_rn(oa.x, oa.y);
        __nv_bfloat162 p1 = __floats2bfloat162_rn(oa.z, oa.w);
        __nv_bfloat162 p2 = __floats2bfloat162_rn(ob.x, ob.y);
        __nv_bfloat162 p3 = __floats2bfloat162_rn(ob.z, ob.w);
        uint4 u;
        u.x = *reinterpret_cast<unsigned*>(&p0);
        u.y = *reinterpret_cast<unsigned*>(&p1);
        u.z = *reinterpret_cast<unsigned*>(&p2);
        u.w = *reinterpret_cast<unsigned*>(&p3);
        reinterpret_cast<uint4*>(houth)[(size_t)nn * 8 + c] = u;
        if (uni) {
            sa.x += oa.x; sa.y += oa.y; sa.z += oa.z; sa.w += oa.w;
            sb.x += ob.x; sb.y += ob.y; sb.z += ob.z; sb.w += ob.w;
        } else {
            int g = sh_b[node];
            float4* pp = reinterpret_cast<float4*>(pooled) + (size_t)g * 128 + c * 2;
            red4(pp, oa);
            red4(pp + 1, ob);
        }
    }
    if (uni) {
        float4* pp = reinterpret_cast<float4*>(pooled) + (size_t)g0 * 128 + c * 2;
        red4(pp, sa);
        red4(pp + 1, sb);
    }
}

// ---------------- classifier head ----------------
__device__ __forceinline__ int lbound(const int* __restrict__ a, int n, int v) {
    int lo = 0, hi = n;
    while (lo < hi) {
        int mid = (lo + hi) >> 1;
        if (a[mid] < v) lo = mid + 1; else hi = mid;
    }
    return lo;
}

__global__ __launch_bounds__(64) void classify_kernel(
        const float* __restrict__ pooled, const int* __restrict__ batch, int N,
        const float* __restrict__ lw1, const float* __restrict__ lb1,
        const float* __restrict__ lw2, const float* __restrict__ lb2,
        float* __restrict__ out) {
    __shared__ float ps[512];
    __shared__ float hid[64];
    __shared__ float lg[3];
    __shared__ float inv;
    int g = blockIdx.x;
    int tid = threadIdx.x;
    if (tid == 0) {
        int a = lbound(batch, N, g);
        int b = lbound(batch, N, g + 1);
        int c = b - a;
        inv = 1.0f / (float)(c > 1 ? c : 1);
    }
    __syncthreads();
    for (int k = tid; k < 512; k += 64) ps[k] = pooled[(size_t)g * 512 + k] * inv;
    __syncthreads();
    float acc = lb1[tid];
#pragma unroll 8
    for (int k = 0; k < 512; ++k) acc = fmaf(ps[k], lw1[k * 64 + tid], acc);
    hid[tid] = fmaxf(acc, 0.f);
    __syncthreads();
    if (tid < 3) {
        float s = lb2[tid];
#pragma unroll
        for (int j = 0; j < 64; ++j) s = fmaf(hid[j], lw2[j * 3 + tid], s);
        lg[tid] = s;
    }
    __syncthreads();
    if (tid == 0) {
        float m = fmaxf(lg[0], fmaxf(lg[1], lg[2]));
        float e = expf(lg[0] - m) + expf(lg[1] - m) + expf(lg[2] - m);
        float lse = m + logf(e);
        out[g * 3 + 0] = lg[0] - lse;
        out[g * 3 + 1] = lg[1] - lse;
        out[g * 3 + 2] = lg[2] - lse;
    }
}

// ---------------- launcher ----------------
extern "C" void kernel_launch(void* const* d_in, const int* in_sizes, int n_in,
                              void* d_out, int out_size) {
    const float* x     = (const float*)d_in[0];
    const int*   ei    = (const int*)d_in[1];
    const int*   batch = (const int*)d_in[2];
    int bi = (in_sizes[3] == 1) ? 4 : 3;
    const float* eps  = (const float*)d_in[bi + 0];
    const float* W1f  = (const float*)d_in[bi + 1];
    const float* W1r  = (const float*)d_in[bi + 2];
    const float* b1   = (const float*)d_in[bi + 3];
    const float* g1   = (const float*)d_in[bi + 4];
    const float* be1  = (const float*)d_in[bi + 5];
    const float* m1   = (const float*)d_in[bi + 6];
    const float* v1   = (const float*)d_in[bi + 7];
    const float* W2   = (const float*)d_in[bi + 8];
    const float* b2   = (const float*)d_in[bi + 9];
    const float* g2   = (const float*)d_in[bi + 10];
    const float* be2  = (const float*)d_in[bi + 11];
    const float* m2   = (const float*)d_in[bi + 12];
    const float* v2   = (const float*)d_in[bi + 13];
    const float* lw1  = (const float*)d_in[bi + 14];
    const float* lb1  = (const float*)d_in[bi + 15];
    const float* lw2  = (const float*)d_in[bi + 16];
    const float* lb2  = (const float*)d_in[bi + 17];

    int N = in_sizes[0];
    int E = in_sizes[1] / 2;
    int G = out_size / 3;
    if (N > MAXN) N = MAXN;
    if (E > MAXE) E = MAXE;
    if (G > MAXG) G = MAXG;

    __nv_bfloat162 *hh0, *hh1;
    float *z, *pooled;
    unsigned* wprep;
    int *deg, *off, *pos, *csr, *bsum;
    cudaGetSymbolAddress((void**)&hh0, g_hh);
    hh1 = hh0 + (size_t)MAXN * 32;
    cudaGetSymbolAddress((void**)&z, g_z);
    cudaGetSymbolAddress((void**)&pooled, g_pooled);
    cudaGetSymbolAddress((void**)&wprep, g_wprep);
    cudaGetSymbolAddress((void**)&deg, g_deg);
    cudaGetSymbolAddress((void**)&off, g_off);
    cudaGetSymbolAddress((void**)&pos, g_pos);
    cudaGetSymbolAddress((void**)&csr, g_csr);
    cudaGetSymbolAddress((void**)&bsum, g_bsum);

    cudaFuncSetAttribute(gin_node_mma, cudaFuncAttributeMaxDynamicSharedMemorySize,
                         MMA_SMEM_U32 * 4);
    cudaFuncSetAttribute(gin_node0, cudaFuncAttributeMaxDynamicSharedMemorySize,
                         NODE0_SMEM_FLOATS * 4);

    int nodeGrid = (N + 127) / 128;
    int edgeGrid = (E + 255) / 256;
    int nScan = N + 1;
    int nb = (nScan + 511) / 512;

    // ----- CSR build + pooled clear + weight prep -----
    cudaMemsetAsync(deg, 0, (size_t)nScan * sizeof(int));
    cudaMemsetAsync(pooled, 0, (size_t)G * 512 * sizeof(float));
    prep_weights<<<7, 128>>>(W1r, W2, wprep);
    deg_count<<<edgeGrid, 256>>>(ei, E, deg);
    chunk_sum<<<nb, 512>>>(deg, nScan, bsum);
    scan_bsum<<<1, 1024>>>(bsum, nb);
    chunk_scan<<<nb, 512>>>(deg, nScan, bsum, off, pos);
    csr_scatter<<<edgeGrid, 256>>>(ei, E, pos, csr);

    // ----- layer 0 (scalar input) -----
    csr_agg1<<<(N + 255) / 256, 256>>>(off, csr, x, z, N);
    gin_node0<<<nodeGrid, 128, NODE0_SMEM_FLOATS * 4>>>(
        x, z, hh0, batch, pooled, eps, W1f,
        b1, g1, be1, m1, v1,
        W2, b2, g2, be2, m2, v2, N);

    // ----- layers 1..7: bf16 gather -> fp32 z -> bf16x2 MMA MLP (+atomic pool) -----
    for (int i = 1; i < LL; ++i) {
        const __nv_bfloat162* hprev = (i & 1) ? hh0 : hh1;
        __nv_bfloat162* hout = (i & 1) ? hh1 : hh0;
        csr_agg_h<<<((size_t)N * 8 + 255) / 256, 256>>>(off, csr, hprev, z, eps + i, N);
        gin_node_mma<<<nodeGrid, 128, MMA_SMEM_U32 * 4>>>(
            z, hout, batch, pooled, i,
            wprep + (size_t)(i - 1) * 9216,
            b1 + i * 64, g1 + i * 64, be1 + i * 64, m1 + i * 64, v1 + i * 64,
            b2 + i * 64, g2 + i * 64, be2 + i * 64, m2 + i * 64, v2 + i * 64, N);
    }

    // ----- head -----
    classify_kernel<<<G, 64>>>(pooled, batch, N, lw1, lb1, lw2, lb2, (float*)d_out);
}

// round 13
// speedup vs baseline: 1.4490x; 1.1022x over previous
#include <cuda_runtime.h>
#include <cuda_bf16.h>
#include <math.h>

#define MAXN 100000
#define MAXE 1600000
#define MAXG 500
#define LL 8
#define BN_EPS 1e-5f

// ---------------- device scratch ----------------
__device__ __nv_bfloat162 g_hh[2][(size_t)MAXN * 32];  // bf16 features, ping-pong (128B rows)
__device__ uint4 g_zhi[(size_t)MAXN * 8];               // z hi split, 32 u32/node
__device__ uint4 g_zlo[(size_t)MAXN * 8];               // z lo split
__device__ float g_agg1[MAXN];                          // layer-0 scalar agg
__device__ float g_pooled[(size_t)MAXG * LL * 64];
__device__ unsigned g_wprep[7 * 9216];                  // split-transposed weights, smem layout
__device__ int g_deg[MAXN + 1];
__device__ int g_off[MAXN + 2];
__device__ int g_pos[MAXN + 1];
__device__ int g_csr[MAXE];
__device__ int g_bsum[1024];

// ---------------- helpers ----------------
__device__ __forceinline__ unsigned long long pack2(float a, float b) {
    unsigned long long r;
    asm("mov.b64 %0, {%1, %2};" : "=l"(r) : "f"(a), "f"(b));
    return r;
}
__device__ __forceinline__ void unpack2(unsigned long long v, float& a, float& b) {
    asm("mov.b64 {%0, %1}, %2;" : "=f"(a), "=f"(b) : "l"(v));
}
__device__ __forceinline__ void fma2(unsigned long long& acc, unsigned long long a, unsigned long long b) {
    asm("fma.rn.f32x2 %0, %1, %2, %0;" : "+l"(acc) : "l"(a), "l"(b));
}
__device__ __forceinline__ void red4(float4* p, float4 v) {
    asm volatile("red.global.add.v4.f32 [%0], {%1, %2, %3, %4};"
                 :: "l"(p), "f"(v.x), "f"(v.y), "f"(v.z), "f"(v.w) : "memory");
}
// split (x,y) into bf16 hi pair + bf16 lo (residual) pair
__device__ __forceinline__ void bfsplit(float x, float y, unsigned& hi, unsigned& lo) {
    __nv_bfloat162 h = __floats2bfloat162_rn(x, y);
    float rx = x - __bfloat162float(h.x);
    float ry = y - __bfloat162float(h.y);
    __nv_bfloat162 l = __floats2bfloat162_rn(rx, ry);
    hi = *reinterpret_cast<unsigned*>(&h);
    lo = *reinterpret_cast<unsigned*>(&l);
}
__device__ __forceinline__ void mma16(float (&c)[4], unsigned a0, unsigned a1, unsigned a2, unsigned a3,
                                      unsigned b0, unsigned b1) {
    asm volatile("mma.sync.aligned.m16n8k16.row.col.f32.bf16.bf16.f32 "
                 "{%0,%1,%2,%3},{%4,%5,%6,%7},{%8,%9},{%0,%1,%2,%3};"
                 : "+f"(c[0]), "+f"(c[1]), "+f"(c[2]), "+f"(c[3])
                 : "r"(a0), "r"(a1), "r"(a2), "r"(a3), "r"(b0), "r"(b1));
}

// ============ CSR build ============
__global__ __launch_bounds__(256) void deg_count(const int* __restrict__ ei, int E, int* __restrict__ deg) {
    int e = blockIdx.x * 256 + threadIdx.x;
    if (e >= E) return;
    atomicAdd(&deg[ei[E + e]], 1);
}

__global__ __launch_bounds__(512) void chunk_sum(const int* __restrict__ deg, int n, int* __restrict__ bsum) {
    __shared__ int sh[512];
    int t = threadIdx.x;
    int i = blockIdx.x * 512 + t;
    sh[t] = (i < n) ? deg[i] : 0;
    __syncthreads();
#pragma unroll
    for (int s = 256; s > 0; s >>= 1) {
        if (t < s) sh[t] += sh[t + s];
        __syncthreads();
    }
    if (t == 0) bsum[blockIdx.x] = sh[0];
}

__global__ __launch_bounds__(1024) void scan_bsum(int* __restrict__ bsum, int nb) {
    __shared__ int sh[1024];
    int t = threadIdx.x;
    int v = (t < nb) ? bsum[t] : 0;
    sh[t] = v;
    __syncthreads();
    for (int d = 1; d < 1024; d <<= 1) {
        int add = (t >= d) ? sh[t - d] : 0;
        __syncthreads();
        sh[t] += add;
        __syncthreads();
    }
    if (t < nb) bsum[t] = sh[t] - v;   // exclusive
}

__global__ __launch_bounds__(512) void chunk_scan(const int* __restrict__ deg, int n,
                                                  const int* __restrict__ bsum,
                                                  int* __restrict__ off, int* __restrict__ pos) {
    __shared__ int sh[512];
    int t = threadIdx.x;
    int i = blockIdx.x * 512 + t;
    int v = (i < n) ? deg[i] : 0;
    sh[t] = v;
    __syncthreads();
    for (int d = 1; d < 512; d <<= 1) {
        int add = (t >= d) ? sh[t - d] : 0;
        __syncthreads();
        sh[t] += add;
        __syncthreads();
    }
    if (i < n) {
        int ex = sh[t] - v + bsum[blockIdx.x];
        off[i] = ex;
        pos[i] = ex;
    }
}

__global__ __launch_bounds__(256) void csr_scatter(const int* __restrict__ ei, int E,
                                                   int* __restrict__ pos, int* __restrict__ csr) {
    int e = blockIdx.x * 256 + threadIdx.x;
    if (e >= E) return;
    int src = ei[e];
    int dst = ei[E + e];
    int p = atomicAdd(&pos[dst], 1);
    csr[p] = src;
}

// ============ weight pre-transform (once per launch) ============
#define AS 36   // row pitch in u32 (32 data + 4 pad)

__global__ __launch_bounds__(128) void prep_weights(const float* __restrict__ W1r,
                                                    const float* __restrict__ W2all,
                                                    unsigned* __restrict__ wprep) {
    int layer = blockIdx.x;                    // 0..6 -> layers 1..7
    const float* W1 = W1r + (size_t)layer * 4096;
    const float* W2 = W2all + (size_t)(layer + 1) * 4096;
    unsigned* dst = wprep + (size_t)layer * 9216;
    for (int idx = threadIdx.x; idx < 2048; idx += 128) {
        int n = idx >> 5, k2 = idx & 31;
        int koff = k2 * 128 + n;
        unsigned hi, lo;
        bfsplit(W1[koff], W1[koff + 64], hi, lo);
        dst[n * AS + k2] = hi;
        dst[2304 + n * AS + k2] = lo;
        bfsplit(W2[koff], W2[koff + 64], hi, lo);
        dst[4608 + n * AS + k2] = hi;
        dst[6912 + n * AS + k2] = lo;
    }
}

// ============ CSR aggregation (bf16 rows -> split-bf16 z) ============
// shift-decode: bf16 bits<<16 == fp32 bits (exact)
__device__ __forceinline__ void addrow_u(uint4 v, float* acc) {
    acc[0] += __uint_as_float(v.x << 16);
    acc[1] += __uint_as_float(v.x & 0xffff0000u);
    acc[2] += __uint_as_float(v.y << 16);
    acc[3] += __uint_as_float(v.y & 0xffff0000u);
    acc[4] += __uint_as_float(v.z << 16);
    acc[5] += __uint_as_float(v.z & 0xffff0000u);
    acc[6] += __uint_as_float(v.w << 16);
    acc[7] += __uint_as_float(v.w & 0xffff0000u);
}

// 8 threads per node, each thread covers 8 contiguous features (16B).
__global__ __launch_bounds__(256) void csr_agg_h(const int* __restrict__ off, const int* __restrict__ csr,
                                                 const __nv_bfloat162* __restrict__ hh,
                                                 uint4* __restrict__ zhi_g, uint4* __restrict__ zlo_g,
                                                 const float* __restrict__ eps, int N) {
    int t = blockIdx.x * 256 + threadIdx.x;
    int n = t >> 3;
    if (n >= N) return;
    int q = t & 7;
    const uint4* hq = reinterpret_cast<const uint4*>(hh) + q;
    float acc[8];
#pragma unroll
    for (int j = 0; j < 8; ++j) acc[j] = 0.f;
    int b = off[n], e = off[n + 1];
    int i = b;
    for (; i + 8 <= e; i += 8) {
        int idx[8];
#pragma unroll
        for (int u = 0; u < 8; ++u) idx[u] = __ldg(&csr[i + u]);
        uint4 v[8];
#pragma unroll
        for (int u = 0; u < 8; ++u) v[u] = hq[idx[u] * 8];
#pragma unroll
        for (int u = 0; u < 8; ++u) addrow_u(v[u], acc);
    }
    for (; i + 4 <= e; i += 4) {
        int i0 = __ldg(&csr[i]);
        int i1 = __ldg(&csr[i + 1]);
        int i2 = __ldg(&csr[i + 2]);
        int i3 = __ldg(&csr[i + 3]);
        uint4 v0 = hq[i0 * 8];
        uint4 v1 = hq[i1 * 8];
        uint4 v2 = hq[i2 * 8];
        uint4 v3 = hq[i3 * 8];
        addrow_u(v0, acc);
        addrow_u(v1, acc);
        addrow_u(v2, acc);
        addrow_u(v3, acc);
    }
    for (; i < e; ++i) addrow_u(hq[__ldg(&csr[i]) * 8], acc);

    // self term
    float ev = 1.0f + eps[0];
    uint4 sv = hq[n * 8];
    float o[8];
    o[0] = fmaf(ev, __uint_as_float(sv.x << 16),          acc[0]);
    o[1] = fmaf(ev, __uint_as_float(sv.x & 0xffff0000u),  acc[1]);
    o[2] = fmaf(ev, __uint_as_float(sv.y << 16),          acc[2]);
    o[3] = fmaf(ev, __uint_as_float(sv.y & 0xffff0000u),  acc[3]);
    o[4] = fmaf(ev, __uint_as_float(sv.z << 16),          acc[4]);
    o[5] = fmaf(ev, __uint_as_float(sv.z & 0xffff0000u),  acc[5]);
    o[6] = fmaf(ev, __uint_as_float(sv.w << 16),          acc[6]);
    o[7] = fmaf(ev, __uint_as_float(sv.w & 0xffff0000u),  acc[7]);

    // split to bf16 hi/lo, one uint4 store per array (coalesced)
    uint4 hi4, lo4;
    bfsplit(o[0], o[1], hi4.x, lo4.x);
    bfsplit(o[2], o[3], hi4.y, lo4.y);
    bfsplit(o[4], o[5], hi4.z, lo4.z);
    bfsplit(o[6], o[7], hi4.w, lo4.w);
    zhi_g[(size_t)n * 8 + q] = hi4;
    zlo_g[(size_t)n * 8 + q] = lo4;
}

// scalar features (layer 0)
__global__ __launch_bounds__(256) void csr_agg1(const int* __restrict__ off, const int* __restrict__ csr,
                                                const float* __restrict__ x, float* __restrict__ agg, int N) {
    int n = blockIdx.x * 256 + threadIdx.x;
    if (n >= N) return;
    int b = off[n], e = off[n + 1];
    float s = 0.f;
    int i = b;
    for (; i + 4 <= e; i += 4) {
        float v0 = x[__ldg(&csr[i])];
        float v1 = x[__ldg(&csr[i + 1])];
        float v2 = x[__ldg(&csr[i + 2])];
        float v3 = x[__ldg(&csr[i + 3])];
        s += (v0 + v1) + (v2 + v3);
    }
    for (; i < e; ++i) s += x[__ldg(&csr[i])];
    agg[n] = s;
}

// ============ BN params ============
__device__ __forceinline__ void load_bn_params(float* prm, int tid,
        const float* b1, const float* g1, const float* be1, const float* m1, const float* v1,
        const float* b2, const float* g2, const float* be2, const float* m2, const float* v2) {
    if (tid < 64) {
        float s1 = g1[tid] * rsqrtf(v1[tid] + BN_EPS);
        prm[tid]       = b1[tid];
        prm[64 + tid]  = s1;
        prm[128 + tid] = fmaf(-m1[tid], s1, be1[tid]);
        float s2 = g2[tid] * rsqrtf(v2[tid] + BN_EPS);
        prm[192 + tid] = b2[tid];
        prm[256 + tid] = s2;
        prm[320 + tid] = fmaf(-m2[tid], s2, be2[tid]);
    }
}

// ============ tensor-core node MLP (layers 1..7), bf16x2 split 3-term ============
#define OFF_W1HI 0
#define OFF_W1LO 2304
#define OFF_W2HI 4608
#define OFF_W2LO 6912
#define OFF_ZHI  9216
#define OFF_ZLO  13824
#define OFF_PRM  18432
#define MMA_SMEM_U32 (18432 + 384)

__device__ __forceinline__ void warp_gemm_bf(const unsigned* __restrict__ Whi,
                                             const unsigned* __restrict__ Wlo,
                                             const unsigned* __restrict__ zhi,
                                             const unsigned* __restrict__ zlo,
                                             int warp, int lane, float acc[2][8][4]) {
    int tig = lane & 3;
    int grp = lane >> 2;
#pragma unroll
    for (int kk = 0; kk < 4; ++kk) {
        int k2a = kk * 8 + tig;
        int k2b = kk * 8 + 4 + tig;
        unsigned bh[8][2], bl[8][2];
#pragma unroll
        for (int nt = 0; nt < 8; ++nt) {
            int n = nt * 8 + grp;
            bh[nt][0] = Whi[n * AS + k2a];
            bh[nt][1] = Whi[n * AS + k2b];
            bl[nt][0] = Wlo[n * AS + k2a];
            bl[nt][1] = Wlo[n * AS + k2b];
        }
#pragma unroll
        for (int mt = 0; mt < 2; ++mt) {
            int r0 = warp * 32 + mt * 16 + grp;
            unsigned ah0 = zhi[r0 * AS + k2a];
            unsigned ah1 = zhi[(r0 + 8) * AS + k2a];
            unsigned ah2 = zhi[r0 * AS + k2b];
            unsigned ah3 = zhi[(r0 + 8) * AS + k2b];
            unsigned al0 = zlo[r0 * AS + k2a];
            unsigned al1 = zlo[(r0 + 8) * AS + k2a];
            unsigned al2 = zlo[r0 * AS + k2b];
            unsigned al3 = zlo[(r0 + 8) * AS + k2b];
#pragma unroll
            for (int nt = 0; nt < 8; ++nt) {
                mma16(acc[mt][nt], ah0, ah1, ah2, ah3, bh[nt][0], bh[nt][1]);
                mma16(acc[mt][nt], ah0, ah1, ah2, ah3, bl[nt][0], bl[nt][1]);
                mma16(acc[mt][nt], al0, al1, al2, al3, bh[nt][0], bh[nt][1]);
            }
        }
    }
}

__global__ __launch_bounds__(128) void gin_node_mma(
        const uint4* __restrict__ zhi_g, const uint4* __restrict__ zlo_g,
        __nv_bfloat162* __restrict__ houth,
        const int* __restrict__ batch, float* __restrict__ pooled, int layer,
        const unsigned* __restrict__ wprep,
        const float* __restrict__ b1,
        const float* __restrict__ g1, const float* __restrict__ be1,
        const float* __restrict__ m1, const float* __restrict__ v1,
        const float* __restrict__ b2,
        const float* __restrict__ g2, const float* __restrict__ be2,
        const float* __restrict__ m2, const float* __restrict__ v2, int N) {
    extern __shared__ unsigned smu[];
    unsigned* W1hi = smu + OFF_W1HI;
    unsigned* W1lo = smu + OFF_W1LO;
    unsigned* W2hi = smu + OFF_W2HI;
    unsigned* W2lo = smu + OFF_W2LO;
    unsigned* zhi  = smu + OFF_ZHI;
    unsigned* zlo  = smu + OFF_ZLO;
    float* prm = reinterpret_cast<float*>(smu + OFF_PRM);
    __shared__ int sh_b[128];
    int tid = threadIdx.x;
    int warp = tid >> 5, lane = tid & 31;
    int tig = lane & 3, grp = lane >> 2;

    // coalesced copy of pre-transposed weights (9216 u32 = 2304 uint4)
    {
        const uint4* wsrc = reinterpret_cast<const uint4*>(wprep);
        uint4* wdst = reinterpret_cast<uint4*>(smu);
#pragma unroll
        for (int i = tid; i < 2304; i += 128) wdst[i] = wsrc[i];
    }
    load_bn_params(prm, tid, b1, g1, be1, m1, v1, b2, g2, be2, m2, v2);

    int n0 = blockIdx.x * 128;
    sh_b[tid] = (n0 + tid < N) ? batch[n0 + tid] : -1;

    // z fill: pure coalesced uint4 copy from pre-split global arrays
    for (int i2 = tid; i2 < 1024; i2 += 128) {
        int row = i2 >> 3, qq = i2 & 7;
        uint4 h4 = make_uint4(0, 0, 0, 0), l4 = make_uint4(0, 0, 0, 0);
        if (n0 + row < N) {
            h4 = zhi_g[(size_t)n0 * 8 + i2];
            l4 = zlo_g[(size_t)n0 * 8 + i2];
        }
        *reinterpret_cast<uint4*>(&zhi[row * AS + qq * 4]) = h4;
        *reinterpret_cast<uint4*>(&zlo[row * AS + qq * 4]) = l4;
    }
    __syncthreads();

    float acc[2][8][4];
#pragma unroll
    for (int mt = 0; mt < 2; ++mt)
#pragma unroll
        for (int nt = 0; nt < 8; ++nt)
#pragma unroll
            for (int p = 0; p < 4; ++p) acc[mt][nt][p] = 0.f;

    warp_gemm_bf(W1hi, W1lo, zhi, zlo, warp, lane, acc);

    // BN1 + ReLU -> back into zs (warp-private rows), zero acc
#pragma unroll
    for (int nt = 0; nt < 8; ++nt) {
        int j = nt * 8 + 2 * tig;
        float b1a = prm[j],       b1b = prm[j + 1];
        float s1a = prm[64 + j],  s1b = prm[64 + j + 1];
        float t1a = prm[128 + j], t1b = prm[128 + j + 1];
        int k2 = nt * 4 + tig;
#pragma unroll
        for (int mt = 0; mt < 2; ++mt) {
            float* C = acc[mt][nt];
            int row = warp * 32 + mt * 16 + grp;
            float y0 = fmaf(fmaxf(C[0] + b1a, 0.f), s1a, t1a);
            float y1 = fmaf(fmaxf(C[1] + b1b, 0.f), s1b, t1b);
            float y2 = fmaf(fmaxf(C[2] + b1a, 0.f), s1a, t1a);
            float y3 = fmaf(fmaxf(C[3] + b1b, 0.f), s1b, t1b);
            unsigned hi, lo;
            bfsplit(y0, y1, hi, lo);
            zhi[row * AS + k2] = hi;
            zlo[row * AS + k2] = lo;
            bfsplit(y2, y3, hi, lo);
            zhi[(row + 8) * AS + k2] = hi;
            zlo[(row + 8) * AS + k2] = lo;
            C[0] = C[1] = C[2] = C[3] = 0.f;
        }
    }
    __syncwarp();

    warp_gemm_bf(W2hi, W2lo, zhi, zlo, warp, lane, acc);

    // warp-uniform graph check over this warp's 32 rows
    int gme = sh_b[warp * 32 + lane];
    int g0 = __shfl_sync(0xffffffffu, gme, 0);
    bool uni = __all_sync(0xffffffffu, gme == g0) && (g0 >= 0);

    // BN2 + bf16 store + pooled RED (scalar atomicAdd)
#pragma unroll
    for (int nt = 0; nt < 8; ++nt) {
        int j = nt * 8 + 2 * tig;
        float b2a = prm[192 + j], b2b = prm[192 + j + 1];
        float s2a = prm[256 + j], s2b = prm[256 + j + 1];
        float t2a = prm[320 + j], t2b = prm[320 + j + 1];
        int jc = j >> 1;
        float p0 = 0.f, p1 = 0.f;
#pragma unroll
        for (int mt = 0; mt < 2; ++mt) {
            float* C = acc[mt][nt];
            int row = warp * 32 + mt * 16 + grp;
            int n = n0 + row;
            if (n < N) {
                float o0 = fmaf(fmaxf(C[0] + b2a, 0.f), s2a, t2a);
                float o1 = fmaf(fmaxf(C[1] + b2b, 0.f), s2b, t2b);
                houth[(size_t)n * 32 + jc] = __floats2bfloat162_rn(o0, o1);
                if (uni) { p0 += o0; p1 += o1; }
                else {
                    float* pp = pooled + (size_t)sh_b[row] * 512 + layer * 64 + j;
                    atomicAdd(pp, o0);
                    atomicAdd(pp + 1, o1);
                }
            }
            if (n + 8 < N) {
                float o2 = fmaf(fmaxf(C[2] + b2a, 0.f), s2a, t2a);
                float o3 = fmaf(fmaxf(C[3] + b2b, 0.f), s2b, t2b);
                houth[(size_t)(n + 8) * 32 + jc] = __floats2bfloat162_rn(o2, o3);
                if (uni) { p0 += o2; p1 += o3; }
                else {
                    float* pp = pooled + (size_t)sh_b[row + 8] * 512 + layer * 64 + j;
                    atomicAdd(pp, o2);
                    atomicAdd(pp + 1, o3);
                }
            }
        }
        if (uni) {
            float* pp = pooled + (size_t)g0 * 512 + layer * 64 + j;
            atomicAdd(pp, p0);
            atomicAdd(pp + 1, p1);
        }
    }
}

// ============ layer 0 (scalar input, FFMA path) ============
#define NODE0_SMEM_FLOATS (4096 + 384 + 64 + 128 * 65)

__device__ __forceinline__ void gemm_tile(const float* __restrict__ Wsh,
                                          const float* __restrict__ zs,
                                          int r, int c, unsigned long long acc[8][4]) {
    const float* zbase = zs + r * 8 * 65;
    const float* wbase = Wsh + c * 8;
#pragma unroll 2
    for (int k = 0; k < 64; ++k) {
        unsigned long long zz[8];
#pragma unroll
        for (int i = 0; i < 8; ++i) {
            float z = zbase[i * 65 + k];
            zz[i] = pack2(z, z);
        }
        ulonglong2 wa = *reinterpret_cast<const ulonglong2*>(wbase + k * 64);
        ulonglong2 wb = *reinterpret_cast<const ulonglong2*>(wbase + k * 64 + 4);
#pragma unroll
        for (int i = 0; i < 8; ++i) {
            fma2(acc[i][0], zz[i], wa.x);
            fma2(acc[i][1], zz[i], wa.y);
            fma2(acc[i][2], zz[i], wb.x);
            fma2(acc[i][3], zz[i], wb.y);
        }
    }
}

__global__ __launch_bounds__(128) void gin_node0(
        const float* __restrict__ x, const float* __restrict__ agg,
        __nv_bfloat162* __restrict__ houth, const int* __restrict__ batch,
        float* __restrict__ pooled, const float* __restrict__ eps,
        const float* __restrict__ W1f, const float* __restrict__ b1,
        const float* __restrict__ g1, const float* __restrict__ be1,
        const float* __restrict__ m1, const float* __restrict__ v1,
        const float* __restrict__ W2, const float* __restrict__ b2,
        const float* __restrict__ g2, const float* __restrict__ be2,
        const float* __restrict__ m2, const float* __restrict__ v2, int N) {
    extern __shared__ float sm[];
    float* W2s = sm;
    float* prm = sm + 4096;
    float* w1f = sm + 4480;
    float* zs  = sm + 4544;
    __shared__ int sh_b[128];
    int tid = threadIdx.x;

    float4* w2d = reinterpret_cast<float4*>(W2s);
    const float4* w2g = reinterpret_cast<const float4*>(W2);
#pragma unroll
    for (int i = tid; i < 1024; i += 128) w2d[i] = w2g[i];
    if (tid < 64) w1f[tid] = W1f[tid];
    load_bn_params(prm, tid, b1, g1, be1, m1, v1, b2, g2, be2, m2, v2);
    __syncthreads();   // w1f/prm/W2s written above, read below

    int n0 = blockIdx.x * 128;
    int n = n0 + tid;
    sh_b[tid] = (n < N) ? batch[n] : -1;
    float* zrow = zs + tid * 65;
    if (n < N) {
        float ev = 1.0f + eps[0];
        float z = fmaf(ev, x[n], agg[n]);
#pragma unroll
        for (int j = 0; j < 64; ++j) {
            float y = fmaxf(fmaf(z, w1f[j], prm[j]), 0.f);
            zrow[j] = fmaf(y, prm[64 + j], prm[128 + j]);
        }
    } else {
#pragma unroll
        for (int j = 0; j < 64; ++j) zrow[j] = 0.f;
    }
    __syncthreads();

    int r = tid >> 3, c = tid & 7;
    unsigned long long acc[8][4];
#pragma unroll
    for (int i = 0; i < 8; ++i)
#pragma unroll
        for (int p = 0; p < 4; ++p) acc[i][p] = 0ull;
    gemm_tile(W2s, zs, r, c, acc);

    float4 b2a = *reinterpret_cast<const float4*>(prm + 192 + c * 8);
    float4 b2b = *reinterpret_cast<const float4*>(prm + 192 + c * 8 + 4);
    float4 s2a = *reinterpret_cast<const float4*>(prm + 256 + c * 8);
    float4 s2b = *reinterpret_cast<const float4*>(prm + 256 + c * 8 + 4);
    float4 t2a = *reinterpret_cast<const float4*>(prm + 320 + c * 8);
    float4 t2b = *reinterpret_cast<const float4*>(prm + 320 + c * 8 + 4);

    int base = r * 8;
    int g0 = sh_b[base];
    bool uni = (n0 + base + 7 < N) && (g0 >= 0);
    if (uni) {
#pragma unroll
        for (int i = 1; i < 8; ++i) uni = uni && (sh_b[base + i] == g0);
    }
    float4 sa = make_float4(0.f, 0.f, 0.f, 0.f);
    float4 sb = make_float4(0.f, 0.f, 0.f, 0.f);

#pragma unroll
    for (int i = 0; i < 8; ++i) {
        int node = base + i;
        int nn = n0 + node;
        if (nn >= N) break;
        float f0, f1, f2, f3, f4, f5, f6, f7;
        unpack2(acc[i][0], f0, f1);
        unpack2(acc[i][1], f2, f3);
        unpack2(acc[i][2], f4, f5);
        unpack2(acc[i][3], f6, f7);
        float4 oa, ob;
        oa.x = fmaf(fmaxf(f0 + b2a.x, 0.f), s2a.x, t2a.x);
        oa.y = fmaf(fmaxf(f1 + b2a.y, 0.f), s2a.y, t2a.y);
        oa.z = fmaf(fmaxf(f2 + b2a.z, 0.f), s2a.z, t2a.z);
        oa.w = fmaf(fmaxf(f3 + b2a.w, 0.f), s2a.w, t2a.w);
        ob.x = fmaf(fmaxf(f4 + b2b.x, 0.f), s2b.x, t2b.x);
        ob.y = fmaf(fmaxf(f5 + b2b.y, 0.f), s2b.y, t2b.y);
        ob.z = fmaf(fmaxf(f6 + b2b.z, 0.f), s2b.z, t2b.z);
        ob.w = fmaf(fmaxf(f7 + b2b.w, 0.f), s2b.w, t2b.w);
        __nv_bfloat162 p0 = __floats2bfloat162_rn(oa.x, oa.y);
        __nv_bfloat162 p1 = __floats2bfloat162_rn(oa.z, oa.w);
        __nv_bfloat162 p2 = __floats2bfloat162_rn(ob.x, ob.y);
        __nv_bfloat162 p3 = __floats2bfloat162_rn(ob.z, ob.w);
        uint4 u;
        u.x = *reinterpret_cast<unsigned*>(&p0);
        u.y = *reinterpret_cast<unsigned*>(&p1);
        u.z = *reinterpret_cast<unsigned*>(&p2);
        u.w = *reinterpret_cast<unsigned*>(&p3);
        reinterpret_cast<uint4*>(houth)[(size_t)nn * 8 + c] = u;
        if (uni) {
            sa.x += oa.x; sa.y += oa.y; sa.z += oa.z; sa.w += oa.w;
            sb.x += ob.x; sb.y += ob.y; sb.z += ob.z; sb.w += ob.w;
        } else {
            int g = sh_b[node];
            float4* pp = reinterpret_cast<float4*>(pooled) + (size_t)g * 128 + c * 2;
            red4(pp, oa);
            red4(pp + 1, ob);
        }
    }
    if (uni) {
        float4* pp = reinterpret_cast<float4*>(pooled) + (size_t)g0 * 128 + c * 2;
        red4(pp, sa);
        red4(pp + 1, sb);
    }
}

// ---------------- classifier head ----------------
__device__ __forceinline__ int lbound(const int* __restrict__ a, int n, int v) {
    int lo = 0, hi = n;
    while (lo < hi) {
        int mid = (lo + hi) >> 1;
        if (a[mid] < v) lo = mid + 1; else hi = mid;
    }
    return lo;
}

__global__ __launch_bounds__(64) void classify_kernel(
        const float* __restrict__ pooled, const int* __restrict__ batch, int N,
        const float* __restrict__ lw1, const float* __restrict__ lb1,
        const float* __restrict__ lw2, const float* __restrict__ lb2,
        float* __restrict__ out) {
    __shared__ float ps[512];
    __shared__ float hid[64];
    __shared__ float lg[3];
    __shared__ float inv;
    int g = blockIdx.x;
    int tid = threadIdx.x;
    if (tid == 0) {
        int a = lbound(batch, N, g);
        int b = lbound(batch, N, g + 1);
        int c = b - a;
        inv = 1.0f / (float)(c > 1 ? c : 1);
    }
    __syncthreads();
    for (int k = tid; k < 512; k += 64) ps[k] = pooled[(size_t)g * 512 + k] * inv;
    __syncthreads();
    float acc = lb1[tid];
#pragma unroll 8
    for (int k = 0; k < 512; ++k) acc = fmaf(ps[k], lw1[k * 64 + tid], acc);
    hid[tid] = fmaxf(acc, 0.f);
    __syncthreads();
    if (tid < 3) {
        float s = lb2[tid];
#pragma unroll
        for (int j = 0; j < 64; ++j) s = fmaf(hid[j], lw2[j * 3 + tid], s);
        lg[tid] = s;
    }
    __syncthreads();
    if (tid == 0) {
        float m = fmaxf(lg[0], fmaxf(lg[1], lg[2]));
        float e = expf(lg[0] - m) + expf(lg[1] - m) + expf(lg[2] - m);
        float lse = m + logf(e);
        out[g * 3 + 0] = lg[0] - lse;
        out[g * 3 + 1] = lg[1] - lse;
        out[g * 3 + 2] = lg[2] - lse;
    }
}

// ---------------- launcher ----------------
extern "C" void kernel_launch(void* const* d_in, const int* in_sizes, int n_in,
                              void* d_out, int out_size) {
    const float* x     = (const float*)d_in[0];
    const int*   ei    = (const int*)d_in[1];
    const int*   batch = (const int*)d_in[2];
    int bi = (in_sizes[3] == 1) ? 4 : 3;
    const float* eps  = (const float*)d_in[bi + 0];
    const float* W1f  = (const float*)d_in[bi + 1];
    const float* W1r  = (const float*)d_in[bi + 2];
    const float* b1   = (const float*)d_in[bi + 3];
    const float* g1   = (const float*)d_in[bi + 4];
    const float* be1  = (const float*)d_in[bi + 5];
    const float* m1   = (const float*)d_in[bi + 6];
    const float* v1   = (const float*)d_in[bi + 7];
    const float* W2   = (const float*)d_in[bi + 8];
    const float* b2   = (const float*)d_in[bi + 9];
    const float* g2   = (const float*)d_in[bi + 10];
    const float* be2  = (const float*)d_in[bi + 11];
    const float* m2   = (const float*)d_in[bi + 12];
    const float* v2   = (const float*)d_in[bi + 13];
    const float* lw1  = (const float*)d_in[bi + 14];
    const float* lb1  = (const float*)d_in[bi + 15];
    const float* lw2  = (const float*)d_in[bi + 16];
    const float* lb2  = (const float*)d_in[bi + 17];

    int N = in_sizes[0];
    int E = in_sizes[1] / 2;
    int G = out_size / 3;
    if (N > MAXN) N = MAXN;
    if (E > MAXE) E = MAXE;
    if (G > MAXG) G = MAXG;

    __nv_bfloat162 *hh0, *hh1;
    uint4 *zhi_g, *zlo_g;
    float *agg1, *pooled;
    unsigned* wprep;
    int *deg, *off, *pos, *csr, *bsum;
    cudaGetSymbolAddress((void**)&hh0, g_hh);
    hh1 = hh0 + (size_t)MAXN * 32;
    cudaGetSymbolAddress((void**)&zhi_g, g_zhi);
    cudaGetSymbolAddress((void**)&zlo_g, g_zlo);
    cudaGetSymbolAddress((void**)&agg1, g_agg1);
    cudaGetSymbolAddress((void**)&pooled, g_pooled);
    cudaGetSymbolAddress((void**)&wprep, g_wprep);
    cudaGetSymbolAddress((void**)&deg, g_deg);
    cudaGetSymbolAddress((void**)&off, g_off);
    cudaGetSymbolAddress((void**)&pos, g_pos);
    cudaGetSymbolAddress((void**)&csr, g_csr);
    cudaGetSymbolAddress((void**)&bsum, g_bsum);

    cudaFuncSetAttribute(gin_node_mma, cudaFuncAttributeMaxDynamicSharedMemorySize,
                         MMA_SMEM_U32 * 4);
    cudaFuncSetAttribute(gin_node0, cudaFuncAttributeMaxDynamicSharedMemorySize,
                         NODE0_SMEM_FLOATS * 4);

    int nodeGrid = (N + 127) / 128;
    int edgeGrid = (E + 255) / 256;
    int nScan = N + 1;
    int nb = (nScan + 511) / 512;

    // ----- CSR build + pooled clear + weight prep -----
    cudaMemsetAsync(deg, 0, (size_t)nScan * sizeof(int));
    cudaMemsetAsync(pooled, 0, (size_t)G * 512 * sizeof(float));
    prep_weights<<<7, 128>>>(W1r, W2, wprep);
    deg_count<<<edgeGrid, 256>>>(ei, E, deg);
    chunk_sum<<<nb, 512>>>(deg, nScan, bsum);
    scan_bsum<<<1, 1024>>>(bsum, nb);
    chunk_scan<<<nb, 512>>>(deg, nScan, bsum, off, pos);
    csr_scatter<<<edgeGrid, 256>>>(ei, E, pos, csr);

    // ----- layer 0 (scalar input) -----
    csr_agg1<<<(N + 255) / 256, 256>>>(off, csr, x, agg1, N);
    gin_node0<<<nodeGrid, 128, NODE0_SMEM_FLOATS * 4>>>(
        x, agg1, hh0, batch, pooled, eps, W1f,
        b1, g1, be1, m1, v1,
        W2, b2, g2, be2, m2, v2, N);

    // ----- layers 1..7: bf16 gather -> split-bf16 z -> bf16x2 MMA MLP -----
    for (int i = 1; i < LL; ++i) {
        const __nv_bfloat162* hprev = (i & 1) ? hh0 : hh1;
        __nv_bfloat162* hout = (i & 1) ? hh1 : hh0;
        csr_agg_h<<<((size_t)N * 8 + 255) / 256, 256>>>(off, csr, hprev, zhi_g, zlo_g, eps + i, N);
        gin_node_mma<<<nodeGrid, 128, MMA_SMEM_U32 * 4>>>(
            zhi_g, zlo_g, hout, batch, pooled, i,
            wprep + (size_t)(i - 1) * 9216,
            b1 + i * 64, g1 + i * 64, be1 + i * 64, m1 + i * 64, v1 + i * 64,
            b2 + i * 64, g2 + i * 64, be2 + i * 64, m2 + i * 64, v2 + i * 64, N);
    }

    // ----- head -----
    classify_kernel<<<G, 64>>>(pooled, batch, N, lw1, lb1, lw2, lb2, (float*)d_out);
}

// round 14
// speedup vs baseline: 1.4610x; 1.0082x over previous
#include <cuda_runtime.h>
#include <cuda_bf16.h>
#include <math.h>

#define MAXN 100000
#define MAXE 1600000
#define MAXG 500
#define LL 8
#define BN_EPS 1e-5f

// ---------------- device scratch ----------------
__device__ __nv_bfloat162 g_hh[2][(size_t)MAXN * 32];  // bf16 features, ping-pong (128B rows)
__device__ uint4 g_zhi[(size_t)MAXN * 8];               // z hi split, 32 u32/node
__device__ uint4 g_zlo[(size_t)MAXN * 8];               // z lo split
__device__ float g_agg1[MAXN];                          // layer-0 scalar agg
__device__ float g_pooled[(size_t)MAXG * LL * 64];
__device__ unsigned g_wprep[7 * 9216];                  // split-transposed weights, smem layout
__device__ unsigned g_w0prep[4608];                     // layer-0 W2 split (hi|lo)
__device__ int g_deg[MAXN + 1];
__device__ int g_off[MAXN + 2];
__device__ int g_pos[MAXN + 1];
__device__ int g_csr[MAXE];
__device__ int g_bsum[1024];

// ---------------- helpers ----------------
__device__ __forceinline__ void bfsplit(float x, float y, unsigned& hi, unsigned& lo) {
    __nv_bfloat162 h = __floats2bfloat162_rn(x, y);
    float rx = x - __bfloat162float(h.x);
    float ry = y - __bfloat162float(h.y);
    __nv_bfloat162 l = __floats2bfloat162_rn(rx, ry);
    hi = *reinterpret_cast<unsigned*>(&h);
    lo = *reinterpret_cast<unsigned*>(&l);
}
__device__ __forceinline__ void mma16(float (&c)[4], unsigned a0, unsigned a1, unsigned a2, unsigned a3,
                                      unsigned b0, unsigned b1) {
    asm volatile("mma.sync.aligned.m16n8k16.row.col.f32.bf16.bf16.f32 "
                 "{%0,%1,%2,%3},{%4,%5,%6,%7},{%8,%9},{%0,%1,%2,%3};"
                 : "+f"(c[0]), "+f"(c[1]), "+f"(c[2]), "+f"(c[3])
                 : "r"(a0), "r"(a1), "r"(a2), "r"(a3), "r"(b0), "r"(b1));
}

// ============ CSR build ============
__global__ __launch_bounds__(256) void deg_count(const int* __restrict__ ei, int E, int* __restrict__ deg) {
    int e = blockIdx.x * 256 + threadIdx.x;
    if (e >= E) return;
    atomicAdd(&deg[ei[E + e]], 1);
}

__global__ __launch_bounds__(512) void chunk_sum(const int* __restrict__ deg, int n, int* __restrict__ bsum) {
    __shared__ int sh[512];
    int t = threadIdx.x;
    int i = blockIdx.x * 512 + t;
    sh[t] = (i < n) ? deg[i] : 0;
    __syncthreads();
#pragma unroll
    for (int s = 256; s > 0; s >>= 1) {
        if (t < s) sh[t] += sh[t + s];
        __syncthreads();
    }
    if (t == 0) bsum[blockIdx.x] = sh[0];
}

__global__ __launch_bounds__(1024) void scan_bsum(int* __restrict__ bsum, int nb) {
    __shared__ int sh[1024];
    int t = threadIdx.x;
    int v = (t < nb) ? bsum[t] : 0;
    sh[t] = v;
    __syncthreads();
    for (int d = 1; d < 1024; d <<= 1) {
        int add = (t >= d) ? sh[t - d] : 0;
        __syncthreads();
        sh[t] += add;
        __syncthreads();
    }
    if (t < nb) bsum[t] = sh[t] - v;   // exclusive
}

__global__ __launch_bounds__(512) void chunk_scan(const int* __restrict__ deg, int n,
                                                  const int* __restrict__ bsum,
                                                  int* __restrict__ off, int* __restrict__ pos) {
    __shared__ int sh[512];
    int t = threadIdx.x;
    int i = blockIdx.x * 512 + t;
    int v = (i < n) ? deg[i] : 0;
    sh[t] = v;
    __syncthreads();
    for (int d = 1; d < 512; d <<= 1) {
        int add = (t >= d) ? sh[t - d] : 0;
        __syncthreads();
        sh[t] += add;
        __syncthreads();
    }
    if (i < n) {
        int ex = sh[t] - v + bsum[blockIdx.x];
        off[i] = ex;
        pos[i] = ex;
    }
}

__global__ __launch_bounds__(256) void csr_scatter(const int* __restrict__ ei, int E,
                                                   int* __restrict__ pos, int* __restrict__ csr) {
    int e = blockIdx.x * 256 + threadIdx.x;
    if (e >= E) return;
    int src = ei[e];
    int dst = ei[E + e];
    int p = atomicAdd(&pos[dst], 1);
    csr[p] = src;
}

// ============ weight pre-transform (once per launch) ============
#define AS 36   // row pitch in u32 (32 data + 4 pad)

__global__ __launch_bounds__(128) void prep_weights(const float* __restrict__ W1r,
                                                    const float* __restrict__ W2all,
                                                    unsigned* __restrict__ wprep) {
    int layer = blockIdx.x;                    // 0..6 -> layers 1..7
    const float* W1 = W1r + (size_t)layer * 4096;
    const float* W2 = W2all + (size_t)(layer + 1) * 4096;
    unsigned* dst = wprep + (size_t)layer * 9216;
    for (int idx = threadIdx.x; idx < 2048; idx += 128) {
        int n = idx >> 5, k2 = idx & 31;
        int koff = k2 * 128 + n;
        unsigned hi, lo;
        bfsplit(W1[koff], W1[koff + 64], hi, lo);
        dst[n * AS + k2] = hi;
        dst[2304 + n * AS + k2] = lo;
        bfsplit(W2[koff], W2[koff + 64], hi, lo);
        dst[4608 + n * AS + k2] = hi;
        dst[6912 + n * AS + k2] = lo;
    }
}

__global__ __launch_bounds__(128) void prep_w0(const float* __restrict__ W2all,
                                               unsigned* __restrict__ w0prep) {
    const float* W2 = W2all;   // layer 0
    for (int idx = threadIdx.x; idx < 2048; idx += 128) {
        int n = idx >> 5, k2 = idx & 31;
        int koff = k2 * 128 + n;
        unsigned hi, lo;
        bfsplit(W2[koff], W2[koff + 64], hi, lo);
        w0prep[n * AS + k2] = hi;
        w0prep[2304 + n * AS + k2] = lo;
    }
}

// ============ CSR aggregation (bf16 rows -> split-bf16 z) ============
__device__ __forceinline__ void addrow_u(uint4 v, float* acc) {
    acc[0] += __uint_as_float(v.x << 16);
    acc[1] += __uint_as_float(v.x & 0xffff0000u);
    acc[2] += __uint_as_float(v.y << 16);
    acc[3] += __uint_as_float(v.y & 0xffff0000u);
    acc[4] += __uint_as_float(v.z << 16);
    acc[5] += __uint_as_float(v.z & 0xffff0000u);
    acc[6] += __uint_as_float(v.w << 16);
    acc[7] += __uint_as_float(v.w & 0xffff0000u);
}

// 8 threads per node, each thread covers 8 contiguous features (16B).
__global__ __launch_bounds__(256) void csr_agg_h(const int* __restrict__ off, const int* __restrict__ csr,
                                                 const __nv_bfloat162* __restrict__ hh,
                                                 uint4* __restrict__ zhi_g, uint4* __restrict__ zlo_g,
                                                 const float* __restrict__ eps, int N) {
    int t = blockIdx.x * 256 + threadIdx.x;
    int n = t >> 3;
    if (n >= N) return;
    int q = t & 7;
    const uint4* hq = reinterpret_cast<const uint4*>(hh) + q;
    float acc[8];
#pragma unroll
    for (int j = 0; j < 8; ++j) acc[j] = 0.f;
    int b = off[n], e = off[n + 1];
    int i = b;
    for (; i + 8 <= e; i += 8) {
        int idx[8];
#pragma unroll
        for (int u = 0; u < 8; ++u) idx[u] = __ldg(&csr[i + u]);
        uint4 v[8];
#pragma unroll
        for (int u = 0; u < 8; ++u) v[u] = hq[idx[u] * 8];
#pragma unroll
        for (int u = 0; u < 8; ++u) addrow_u(v[u], acc);
    }
    for (; i + 4 <= e; i += 4) {
        int i0 = __ldg(&csr[i]);
        int i1 = __ldg(&csr[i + 1]);
        int i2 = __ldg(&csr[i + 2]);
        int i3 = __ldg(&csr[i + 3]);
        uint4 v0 = hq[i0 * 8];
        uint4 v1 = hq[i1 * 8];
        uint4 v2 = hq[i2 * 8];
        uint4 v3 = hq[i3 * 8];
        addrow_u(v0, acc);
        addrow_u(v1, acc);
        addrow_u(v2, acc);
        addrow_u(v3, acc);
    }
    for (; i < e; ++i) addrow_u(hq[__ldg(&csr[i]) * 8], acc);

    float ev = 1.0f + eps[0];
    uint4 sv = hq[n * 8];
    float o[8];
    o[0] = fmaf(ev, __uint_as_float(sv.x << 16),          acc[0]);
    o[1] = fmaf(ev, __uint_as_float(sv.x & 0xffff0000u),  acc[1]);
    o[2] = fmaf(ev, __uint_as_float(sv.y << 16),          acc[2]);
    o[3] = fmaf(ev, __uint_as_float(sv.y & 0xffff0000u),  acc[3]);
    o[4] = fmaf(ev, __uint_as_float(sv.z << 16),          acc[4]);
    o[5] = fmaf(ev, __uint_as_float(sv.z & 0xffff0000u),  acc[5]);
    o[6] = fmaf(ev, __uint_as_float(sv.w << 16),          acc[6]);
    o[7] = fmaf(ev, __uint_as_float(sv.w & 0xffff0000u),  acc[7]);

    uint4 hi4, lo4;
    bfsplit(o[0], o[1], hi4.x, lo4.x);
    bfsplit(o[2], o[3], hi4.y, lo4.y);
    bfsplit(o[4], o[5], hi4.z, lo4.z);
    bfsplit(o[6], o[7], hi4.w, lo4.w);
    zhi_g[(size_t)n * 8 + q] = hi4;
    zlo_g[(size_t)n * 8 + q] = lo4;
}

// scalar features (layer 0)
__global__ __launch_bounds__(256) void csr_agg1(const int* __restrict__ off, const int* __restrict__ csr,
                                                const float* __restrict__ x, float* __restrict__ agg, int N) {
    int n = blockIdx.x * 256 + threadIdx.x;
    if (n >= N) return;
    int b = off[n], e = off[n + 1];
    float s = 0.f;
    int i = b;
    for (; i + 4 <= e; i += 4) {
        float v0 = x[__ldg(&csr[i])];
        float v1 = x[__ldg(&csr[i + 1])];
        float v2 = x[__ldg(&csr[i + 2])];
        float v3 = x[__ldg(&csr[i + 3])];
        s += (v0 + v1) + (v2 + v3);
    }
    for (; i < e; ++i) s += x[__ldg(&csr[i])];
    agg[n] = s;
}

// layer 0 MLP1+BN1: 8 threads/node, thread q handles features [8q, 8q+8)
__global__ __launch_bounds__(256) void node0_prep(
        const float* __restrict__ x, const float* __restrict__ agg,
        uint4* __restrict__ zhi_g, uint4* __restrict__ zlo_g,
        const float* __restrict__ eps, const float* __restrict__ W1f,
        const float* __restrict__ b1, const float* __restrict__ g1,
        const float* __restrict__ be1, const float* __restrict__ m1,
        const float* __restrict__ v1, int N) {
    int t = blockIdx.x * 256 + threadIdx.x;
    int n = t >> 3;
    if (n >= N) return;
    int q = t & 7;
    float ev = 1.0f + eps[0];
    float z = fmaf(ev, x[n], agg[n]);
    float o[8];
#pragma unroll
    for (int u = 0; u < 8; ++u) {
        int j = q * 8 + u;
        float s1 = __ldg(&g1[j]) * rsqrtf(__ldg(&v1[j]) + BN_EPS);
        float t1 = fmaf(-__ldg(&m1[j]), s1, __ldg(&be1[j]));
        float y = fmaxf(fmaf(z, __ldg(&W1f[j]), __ldg(&b1[j])), 0.f);
        o[u] = fmaf(y, s1, t1);
    }
    uint4 hi4, lo4;
    bfsplit(o[0], o[1], hi4.x, lo4.x);
    bfsplit(o[2], o[3], hi4.y, lo4.y);
    bfsplit(o[4], o[5], hi4.z, lo4.z);
    bfsplit(o[6], o[7], hi4.w, lo4.w);
    zhi_g[(size_t)n * 8 + q] = hi4;
    zlo_g[(size_t)n * 8 + q] = lo4;
}

// ============ BN params ============
__device__ __forceinline__ void load_bn_params(float* prm, int tid,
        const float* b1, const float* g1, const float* be1, const float* m1, const float* v1,
        const float* b2, const float* g2, const float* be2, const float* m2, const float* v2) {
    if (tid < 64) {
        float s1 = g1[tid] * rsqrtf(v1[tid] + BN_EPS);
        prm[tid]       = b1[tid];
        prm[64 + tid]  = s1;
        prm[128 + tid] = fmaf(-m1[tid], s1, be1[tid]);
        float s2 = g2[tid] * rsqrtf(v2[tid] + BN_EPS);
        prm[192 + tid] = b2[tid];
        prm[256 + tid] = s2;
        prm[320 + tid] = fmaf(-m2[tid], s2, be2[tid]);
    }
}

// ============ tensor-core node MLP, bf16x2 split 3-term ============
#define OFF_W1HI 0
#define OFF_W1LO 2304
#define OFF_W2HI 4608
#define OFF_W2LO 6912
#define OFF_ZHI  9216
#define OFF_ZLO  13824
#define OFF_PRM  18432
#define MMA_SMEM_U32 (18432 + 384)

__device__ __forceinline__ void warp_gemm_bf(const unsigned* __restrict__ Whi,
                                             const unsigned* __restrict__ Wlo,
                                             const unsigned* __restrict__ zhi,
                                             const unsigned* __restrict__ zlo,
                                             int warp, int lane, float acc[2][8][4]) {
    int tig = lane & 3;
    int grp = lane >> 2;
#pragma unroll
    for (int kk = 0; kk < 4; ++kk) {
        int k2a = kk * 8 + tig;
        int k2b = kk * 8 + 4 + tig;
        unsigned bh[8][2], bl[8][2];
#pragma unroll
        for (int nt = 0; nt < 8; ++nt) {
            int n = nt * 8 + grp;
            bh[nt][0] = Whi[n * AS + k2a];
            bh[nt][1] = Whi[n * AS + k2b];
            bl[nt][0] = Wlo[n * AS + k2a];
            bl[nt][1] = Wlo[n * AS + k2b];
        }
#pragma unroll
        for (int mt = 0; mt < 2; ++mt) {
            int r0 = warp * 32 + mt * 16 + grp;
            unsigned ah0 = zhi[r0 * AS + k2a];
            unsigned ah1 = zhi[(r0 + 8) * AS + k2a];
            unsigned ah2 = zhi[r0 * AS + k2b];
            unsigned ah3 = zhi[(r0 + 8) * AS + k2b];
            unsigned al0 = zlo[r0 * AS + k2a];
            unsigned al1 = zlo[(r0 + 8) * AS + k2a];
            unsigned al2 = zlo[r0 * AS + k2b];
            unsigned al3 = zlo[(r0 + 8) * AS + k2b];
#pragma unroll
            for (int nt = 0; nt < 8; ++nt) {
                mma16(acc[mt][nt], ah0, ah1, ah2, ah3, bh[nt][0], bh[nt][1]);
                mma16(acc[mt][nt], ah0, ah1, ah2, ah3, bl[nt][0], bl[nt][1]);
                mma16(acc[mt][nt], al0, al1, al2, al3, bh[nt][0], bh[nt][1]);
            }
        }
    }
}

// shared epilogue: BN2 + bf16 store + pooled RED (warp-prereduced atomics)
__device__ __forceinline__ void mma_epilogue(float acc[2][8][4], const float* prm,
                                             const int* sh_b, int n0, int warp, int lane,
                                             int tig, int grp, int N, int layer,
                                             __nv_bfloat162* houth, float* pooled) {
    int gme = sh_b[warp * 32 + lane];
    int g0 = __shfl_sync(0xffffffffu, gme, 0);
    bool uni = __all_sync(0xffffffffu, gme == g0) && (g0 >= 0);

#pragma unroll
    for (int nt = 0; nt < 8; ++nt) {
        int j = nt * 8 + 2 * tig;
        float b2a = prm[192 + j], b2b = prm[192 + j + 1];
        float s2a = prm[256 + j], s2b = prm[256 + j + 1];
        float t2a = prm[320 + j], t2b = prm[320 + j + 1];
        int jc = j >> 1;
        float p0 = 0.f, p1 = 0.f;
#pragma unroll
        for (int mt = 0; mt < 2; ++mt) {
            float* C = acc[mt][nt];
            int row = warp * 32 + mt * 16 + grp;
            int n = n0 + row;
            if (n < N) {
                float o0 = fmaf(fmaxf(C[0] + b2a, 0.f), s2a, t2a);
                float o1 = fmaf(fmaxf(C[1] + b2b, 0.f), s2b, t2b);
                houth[(size_t)n * 32 + jc] = __floats2bfloat162_rn(o0, o1);
                if (uni) { p0 += o0; p1 += o1; }
                else {
                    float* pp = pooled + (size_t)sh_b[row] * 512 + layer * 64 + j;
                    atomicAdd(pp, o0);
                    atomicAdd(pp + 1, o1);
                }
            }
            if (n + 8 < N) {
                float o2 = fmaf(fmaxf(C[2] + b2a, 0.f), s2a, t2a);
                float o3 = fmaf(fmaxf(C[3] + b2b, 0.f), s2b, t2b);
                houth[(size_t)(n + 8) * 32 + jc] = __floats2bfloat162_rn(o2, o3);
                if (uni) { p0 += o2; p1 += o3; }
                else {
                    float* pp = pooled + (size_t)sh_b[row + 8] * 512 + layer * 64 + j;
                    atomicAdd(pp, o2);
                    atomicAdd(pp + 1, o3);
                }
            }
        }
        if (uni) {
            // combine across grp (lanes with equal tig share j and g0)
            p0 += __shfl_xor_sync(0xffffffffu, p0, 4);
            p1 += __shfl_xor_sync(0xffffffffu, p1, 4);
            p0 += __shfl_xor_sync(0xffffffffu, p0, 8);
            p1 += __shfl_xor_sync(0xffffffffu, p1, 8);
            p0 += __shfl_xor_sync(0xffffffffu, p0, 16);
            p1 += __shfl_xor_sync(0xffffffffu, p1, 16);
            if (grp == 0) {
                float* pp = pooled + (size_t)g0 * 512 + layer * 64 + j;
                atomicAdd(pp, p0);
                atomicAdd(pp + 1, p1);
            }
        }
    }
}

__global__ __launch_bounds__(128) void gin_node_mma(
        const uint4* __restrict__ zhi_g, const uint4* __restrict__ zlo_g,
        __nv_bfloat162* __restrict__ houth,
        const int* __restrict__ batch, float* __restrict__ pooled, int layer,
        const unsigned* __restrict__ wprep,
        const float* __restrict__ b1,
        const float* __restrict__ g1, const float* __restrict__ be1,
        const float* __restrict__ m1, const float* __restrict__ v1,
        const float* __restrict__ b2,
        const float* __restrict__ g2, const float* __restrict__ be2,
        const float* __restrict__ m2, const float* __restrict__ v2, int N) {
    extern __shared__ unsigned smu[];
    unsigned* W1hi = smu + OFF_W1HI;
    unsigned* W1lo = smu + OFF_W1LO;
    unsigned* W2hi = smu + OFF_W2HI;
    unsigned* W2lo = smu + OFF_W2LO;
    unsigned* zhi  = smu + OFF_ZHI;
    unsigned* zlo  = smu + OFF_ZLO;
    float* prm = reinterpret_cast<float*>(smu + OFF_PRM);
    __shared__ int sh_b[128];
    int tid = threadIdx.x;
    int warp = tid >> 5, lane = tid & 31;
    int tig = lane & 3, grp = lane >> 2;

    {
        const uint4* wsrc = reinterpret_cast<const uint4*>(wprep);
        uint4* wdst = reinterpret_cast<uint4*>(smu);
#pragma unroll
        for (int i = tid; i < 2304; i += 128) wdst[i] = wsrc[i];
    }
    load_bn_params(prm, tid, b1, g1, be1, m1, v1, b2, g2, be2, m2, v2);

    int n0 = blockIdx.x * 128;
    sh_b[tid] = (n0 + tid < N) ? batch[n0 + tid] : -1;

    for (int i2 = tid; i2 < 1024; i2 += 128) {
        int row = i2 >> 3, qq = i2 & 7;
        uint4 h4 = make_uint4(0, 0, 0, 0), l4 = make_uint4(0, 0, 0, 0);
        if (n0 + row < N) {
            h4 = zhi_g[(size_t)n0 * 8 + i2];
            l4 = zlo_g[(size_t)n0 * 8 + i2];
        }
        *reinterpret_cast<uint4*>(&zhi[row * AS + qq * 4]) = h4;
        *reinterpret_cast<uint4*>(&zlo[row * AS + qq * 4]) = l4;
    }
    __syncthreads();

    float acc[2][8][4];
#pragma unroll
    for (int mt = 0; mt < 2; ++mt)
#pragma unroll
        for (int nt = 0; nt < 8; ++nt)
#pragma unroll
            for (int p = 0; p < 4; ++p) acc[mt][nt][p] = 0.f;

    warp_gemm_bf(W1hi, W1lo, zhi, zlo, warp, lane, acc);

    // BN1 + ReLU -> back into zs (warp-private rows), zero acc
#pragma unroll
    for (int nt = 0; nt < 8; ++nt) {
        int j = nt * 8 + 2 * tig;
        float b1a = prm[j],       b1b = prm[j + 1];
        float s1a = prm[64 + j],  s1b = prm[64 + j + 1];
        float t1a = prm[128 + j], t1b = prm[128 + j + 1];
        int k2 = nt * 4 + tig;
#pragma unroll
        for (int mt = 0; mt < 2; ++mt) {
            float* C = acc[mt][nt];
            int row = warp * 32 + mt * 16 + grp;
            float y0 = fmaf(fmaxf(C[0] + b1a, 0.f), s1a, t1a);
            float y1 = fmaf(fmaxf(C[1] + b1b, 0.f), s1b, t1b);
            float y2 = fmaf(fmaxf(C[2] + b1a, 0.f), s1a, t1a);
            float y3 = fmaf(fmaxf(C[3] + b1b, 0.f), s1b, t1b);
            unsigned hi, lo;
            bfsplit(y0, y1, hi, lo);
            zhi[row * AS + k2] = hi;
            zlo[row * AS + k2] = lo;
            bfsplit(y2, y3, hi, lo);
            zhi[(row + 8) * AS + k2] = hi;
            zlo[(row + 8) * AS + k2] = lo;
            C[0] = C[1] = C[2] = C[3] = 0.f;
        }
    }
    __syncwarp();

    warp_gemm_bf(W2hi, W2lo, zhi, zlo, warp, lane, acc);
    mma_epilogue(acc, prm, sh_b, n0, warp, lane, tig, grp, N, layer, houth, pooled);
}

// layer 0 node kernel: GEMM2-only (z buffers already hold BN1(ReLU(MLP1)))
__global__ __launch_bounds__(128) void gin_node0_mma(
        const uint4* __restrict__ zhi_g, const uint4* __restrict__ zlo_g,
        __nv_bfloat162* __restrict__ houth,
        const int* __restrict__ batch, float* __restrict__ pooled,
        const unsigned* __restrict__ w0prep,
        const float* __restrict__ b1,
        const float* __restrict__ g1, const float* __restrict__ be1,
        const float* __restrict__ m1, const float* __restrict__ v1,
        const float* __restrict__ b2,
        const float* __restrict__ g2, const float* __restrict__ be2,
        const float* __restrict__ m2, const float* __restrict__ v2, int N) {
    extern __shared__ unsigned smu[];
    unsigned* W2hi = smu + OFF_W2HI;
    unsigned* W2lo = smu + OFF_W2LO;
    unsigned* zhi  = smu + OFF_ZHI;
    unsigned* zlo  = smu + OFF_ZLO;
    float* prm = reinterpret_cast<float*>(smu + OFF_PRM);
    __shared__ int sh_b[128];
    int tid = threadIdx.x;
    int warp = tid >> 5, lane = tid & 31;
    int tig = lane & 3, grp = lane >> 2;

    // copy W2 split (4608 u32 contiguous) into W2hi|W2lo region
    {
        const uint4* wsrc = reinterpret_cast<const uint4*>(w0prep);
        uint4* wdst = reinterpret_cast<uint4*>(smu + OFF_W2HI);
#pragma unroll
        for (int i = tid; i < 1152; i += 128) wdst[i] = wsrc[i];
    }
    load_bn_params(prm, tid, b1, g1, be1, m1, v1, b2, g2, be2, m2, v2);

    int n0 = blockIdx.x * 128;
    sh_b[tid] = (n0 + tid < N) ? batch[n0 + tid] : -1;

    for (int i2 = tid; i2 < 1024; i2 += 128) {
        int row = i2 >> 3, qq = i2 & 7;
        uint4 h4 = make_uint4(0, 0, 0, 0), l4 = make_uint4(0, 0, 0, 0);
        if (n0 + row < N) {
            h4 = zhi_g[(size_t)n0 * 8 + i2];
            l4 = zlo_g[(size_t)n0 * 8 + i2];
        }
        *reinterpret_cast<uint4*>(&zhi[row * AS + qq * 4]) = h4;
        *reinterpret_cast<uint4*>(&zlo[row * AS + qq * 4]) = l4;
    }
    __syncthreads();

    float acc[2][8][4];
#pragma unroll
    for (int mt = 0; mt < 2; ++mt)
#pragma unroll
        for (int nt = 0; nt < 8; ++nt)
#pragma unroll
            for (int p = 0; p < 4; ++p) acc[mt][nt][p] = 0.f;

    warp_gemm_bf(W2hi, W2lo, zhi, zlo, warp, lane, acc);
    mma_epilogue(acc, prm, sh_b, n0, warp, lane, tig, grp, N, 0, houth, pooled);
}

// ---------------- classifier head ----------------
__device__ __forceinline__ int lbound(const int* __restrict__ a, int n, int v) {
    int lo = 0, hi = n;
    while (lo < hi) {
        int mid = (lo + hi) >> 1;
        if (a[mid] < v) lo = mid + 1; else hi = mid;
    }
    return lo;
}

__global__ __launch_bounds__(64) void classify_kernel(
        const float* __restrict__ pooled, const int* __restrict__ batch, int N,
        const float* __restrict__ lw1, const float* __restrict__ lb1,
        const float* __restrict__ lw2, const float* __restrict__ lb2,
        float* __restrict__ out) {
    __shared__ float ps[512];
    __shared__ float hid[64];
    __shared__ float lg[3];
    __shared__ float inv;
    int g = blockIdx.x;
    int tid = threadIdx.x;
    if (tid == 0) {
        int a = lbound(batch, N, g);
        int b = lbound(batch, N, g + 1);
        int c = b - a;
        inv = 1.0f / (float)(c > 1 ? c : 1);
    }
    __syncthreads();
    for (int k = tid; k < 512; k += 64) ps[k] = pooled[(size_t)g * 512 + k] * inv;
    __syncthreads();
    float acc = lb1[tid];
#pragma unroll 8
    for (int k = 0; k < 512; ++k) acc = fmaf(ps[k], lw1[k * 64 + tid], acc);
    hid[tid] = fmaxf(acc, 0.f);
    __syncthreads();
    if (tid < 3) {
        float s = lb2[tid];
#pragma unroll
        for (int j = 0; j < 64; ++j) s = fmaf(hid[j], lw2[j * 3 + tid], s);
        lg[tid] = s;
    }
    __syncthreads();
    if (tid == 0) {
        float m = fmaxf(lg[0], fmaxf(lg[1], lg[2]));
        float e = expf(lg[0] - m) + expf(lg[1] - m) + expf(lg[2] - m);
        float lse = m + logf(e);
        out[g * 3 + 0] = lg[0] - lse;
        out[g * 3 + 1] = lg[1] - lse;
        out[g * 3 + 2] = lg[2] - lse;
    }
}

// ---------------- launcher ----------------
extern "C" void kernel_launch(void* const* d_in, const int* in_sizes, int n_in,
                              void* d_out, int out_size) {
    const float* x     = (const float*)d_in[0];
    const int*   ei    = (const int*)d_in[1];
    const int*   batch = (const int*)d_in[2];
    int bi = (in_sizes[3] == 1) ? 4 : 3;
    const float* eps  = (const float*)d_in[bi + 0];
    const float* W1f  = (const float*)d_in[bi + 1];
    const float* W1r  = (const float*)d_in[bi + 2];
    const float* b1   = (const float*)d_in[bi + 3];
    const float* g1   = (const float*)d_in[bi + 4];
    const float* be1  = (const float*)d_in[bi + 5];
    const float* m1   = (const float*)d_in[bi + 6];
    const float* v1   = (const float*)d_in[bi + 7];
    const float* W2   = (const float*)d_in[bi + 8];
    const float* b2   = (const float*)d_in[bi + 9];
    const float* g2   = (const float*)d_in[bi + 10];
    const float* be2  = (const float*)d_in[bi + 11];
    const float* m2   = (const float*)d_in[bi + 12];
    const float* v2   = (const float*)d_in[bi + 13];
    const float* lw1  = (const float*)d_in[bi + 14];
    const float* lb1  = (const float*)d_in[bi + 15];
    const float* lw2  = (const float*)d_in[bi + 16];
    const float* lb2  = (const float*)d_in[bi + 17];

    int N = in_sizes[0];
    int E = in_sizes[1] / 2;
    int G = out_size / 3;
    if (N > MAXN) N = MAXN;
    if (E > MAXE) E = MAXE;
    if (G > MAXG) G = MAXG;

    __nv_bfloat162 *hh0, *hh1;
    uint4 *zhi_g, *zlo_g;
    float *agg1, *pooled;
    unsigned *wprep, *w0prep;
    int *deg, *off, *pos, *csr, *bsum;
    cudaGetSymbolAddress((void**)&hh0, g_hh);
    hh1 = hh0 + (size_t)MAXN * 32;
    cudaGetSymbolAddress((void**)&zhi_g, g_zhi);
    cudaGetSymbolAddress((void**)&zlo_g, g_zlo);
    cudaGetSymbolAddress((void**)&agg1, g_agg1);
    cudaGetSymbolAddress((void**)&pooled, g_pooled);
    cudaGetSymbolAddress((void**)&wprep, g_wprep);
    cudaGetSymbolAddress((void**)&w0prep, g_w0prep);
    cudaGetSymbolAddress((void**)&deg, g_deg);
    cudaGetSymbolAddress((void**)&off, g_off);
    cudaGetSymbolAddress((void**)&pos, g_pos);
    cudaGetSymbolAddress((void**)&csr, g_csr);
    cudaGetSymbolAddress((void**)&bsum, g_bsum);

    cudaFuncSetAttribute(gin_node_mma, cudaFuncAttributeMaxDynamicSharedMemorySize,
                         MMA_SMEM_U32 * 4);
    cudaFuncSetAttribute(gin_node0_mma, cudaFuncAttributeMaxDynamicSharedMemorySize,
                         MMA_SMEM_U32 * 4);

    int nodeGrid = (N + 127) / 128;
    int edgeGrid = (E + 255) / 256;
    int nScan = N + 1;
    int nb = (nScan + 511) / 512;

    // ----- CSR build + pooled clear + weight prep -----
    cudaMemsetAsync(deg, 0, (size_t)nScan * sizeof(int));
    cudaMemsetAsync(pooled, 0, (size_t)G * 512 * sizeof(float));
    prep_weights<<<7, 128>>>(W1r, W2, wprep);
    prep_w0<<<1, 128>>>(W2, w0prep);
    deg_count<<<edgeGrid, 256>>>(ei, E, deg);
    chunk_sum<<<nb, 512>>>(deg, nScan, bsum);
    scan_bsum<<<1, 1024>>>(bsum, nb);
    chunk_scan<<<nb, 512>>>(deg, nScan, bsum, off, pos);
    csr_scatter<<<edgeGrid, 256>>>(ei, E, pos, csr);

    // ----- layer 0 (scalar input) -----
    csr_agg1<<<(N + 255) / 256, 256>>>(off, csr, x, agg1, N);
    node0_prep<<<((size_t)N * 8 + 255) / 256, 256>>>(
        x, agg1, zhi_g, zlo_g, eps, W1f, b1, g1, be1, m1, v1, N);
    gin_node0_mma<<<nodeGrid, 128, MMA_SMEM_U32 * 4>>>(
        zhi_g, zlo_g, hh0, batch, pooled, w0prep,
        b1, g1, be1, m1, v1,
        b2, g2, be2, m2, v2, N);

    // ----- layers 1..7: bf16 gather -> split-bf16 z -> bf16x2 MMA MLP -----
    for (int i = 1; i < LL; ++i) {
        const __nv_bfloat162* hprev = (i & 1) ? hh0 : hh1;
        __nv_bfloat162* hout = (i & 1) ? hh1 : hh0;
        csr_agg_h<<<((size_t)N * 8 + 255) / 256, 256>>>(off, csr, hprev, zhi_g, zlo_g, eps + i, N);
        gin_node_mma<<<nodeGrid, 128, MMA_SMEM_U32 * 4>>>(
            zhi_g, zlo_g, hout, batch, pooled, i,
            wprep + (size_t)(i - 1) * 9216,
            b1 + i * 64, g1 + i * 64, be1 + i * 64, m1 + i * 64, v1 + i * 64,
            b2 + i * 64, g2 + i * 64, be2 + i * 64, m2 + i * 64, v2 + i * 64, N);
    }

    // ----- head -----
    classify_kernel<<<G, 64>>>(pooled, batch, N, lw1, lb1, lw2, lb2, (float*)d_out);
}